// round 2
// baseline (speedup 1.0000x reference)
#include <cuda_runtime.h>
#include <math.h>

#define BB 16
#define CC 512
#define HWD 1024
#define NG 32
#define CPG 16   // channels per group

// Scratch (allocation-free: __device__ globals)
__device__ float g_xn[(size_t)BB*CC*HWD];
__device__ float g_q [(size_t)BB*CC*HWD];
__device__ float g_k [(size_t)BB*CC*HWD];
__device__ float g_v [(size_t)BB*CC*HWD];
__device__ float g_e [(size_t)BB*HWD*HWD];
__device__ float g_o [(size_t)BB*CC*HWD];

// ---------------- GroupNorm: one block per (b, group) ----------------
__global__ void groupnorm_kernel(const float* __restrict__ x,
                                 const float* __restrict__ gamma,
                                 const float* __restrict__ beta,
                                 float* __restrict__ out)
{
    int grp = blockIdx.x;           // 0..511 = b*32 + g
    int g = grp & 31;
    const int n = CPG * HWD;        // 16384
    size_t base = (size_t)grp * CPG * HWD;
    const float* xp = x + base;
    float s = 0.f, ss = 0.f;
    for (int i = threadIdx.x; i < n; i += 256) {
        float v = xp[i];
        s += v; ss += v * v;
    }
    __shared__ float rs[256], rss[256];
    rs[threadIdx.x] = s; rss[threadIdx.x] = ss;
    __syncthreads();
    for (int off = 128; off > 0; off >>= 1) {
        if (threadIdx.x < off) {
            rs[threadIdx.x]  += rs[threadIdx.x + off];
            rss[threadIdx.x] += rss[threadIdx.x + off];
        }
        __syncthreads();
    }
    float mean = rs[0] / n;
    float var  = rss[0] / n - mean * mean;
    float inv  = rsqrtf(var + 1e-6f);
    float* op = out + base;
    for (int i = threadIdx.x; i < n; i += 256) {
        int c = g * CPG + (i >> 10);
        op[i] = (xp[i] - mean) * inv * gamma[c] + beta[c];
    }
}

// ---------------- Row softmax: one block per row of 1024 ----------------
__global__ void softmax_kernel(float* __restrict__ e)
{
    float4* r4 = (float4*)(e + (size_t)blockIdx.x * HWD);
    int t = threadIdx.x;
    float4 v = r4[t];
    float m = fmaxf(fmaxf(v.x, v.y), fmaxf(v.z, v.w));
    __shared__ float red[256];
    red[t] = m; __syncthreads();
    for (int off = 128; off > 0; off >>= 1) {
        if (t < off) red[t] = fmaxf(red[t], red[t + off]);
        __syncthreads();
    }
    m = red[0];
    __syncthreads();
    v.x = __expf(v.x - m); v.y = __expf(v.y - m);
    v.z = __expf(v.z - m); v.w = __expf(v.w - m);
    float s = v.x + v.y + v.z + v.w;
    red[t] = s; __syncthreads();
    for (int off = 128; off > 0; off >>= 1) {
        if (t < off) red[t] += red[t + off];
        __syncthreads();
    }
    float invs = 1.f / red[0];
    v.x *= invs; v.y *= invs; v.z *= invs; v.w *= invs;
    r4[t] = v;
}

// ---------------- Generic batched SGEMM, 128x128x8 tile, 8x8/thread ----------------
// C[m,n] = alpha * sum_k opA(m,k)*opB(k,n)  (+ bias[m]) (+ res[m,n])
// AT: A[k*lda + m] else A[m*lda + k];  BT: B[n*ldb + k] else B[k*ldb + n]. ldc == N.
template<bool AT, bool BT, bool BIAS, bool RES>
__global__ void __launch_bounds__(256)
gemm_kernel(const float* __restrict__ A, const float* __restrict__ B,
            float* __restrict__ C, const float* __restrict__ bias,
            const float* __restrict__ res,
            int M, int N, int K, int lda, int ldb,
            long long sA, long long sB, long long sC, float alpha)
{
    __shared__ float As[8][128];
    __shared__ float Bs[8][128];
    long long z = blockIdx.z;
    A += z * sA; B += z * sB; C += z * sC;
    const float* resp = RES ? (res + z * sC) : nullptr;
    int bm = blockIdx.y * 128;
    int bn = blockIdx.x * 128;
    int tid = threadIdx.x;
    int tr = tid >> 4;     // 0..15 -> row group
    int tc = tid & 15;     // 0..15 -> col group
    float acc[8][8] = {};

    for (int k0 = 0; k0 < K; k0 += 8) {
        if (AT) {
            int aK = tid >> 5;              // 0..7
            int aM = (tid & 31) << 2;       // 0..124
            float4 va = *(const float4*)&A[(size_t)(k0 + aK) * lda + bm + aM];
            *(float4*)&As[aK][aM] = va;
        } else {
            int aR = tid >> 1;              // 0..127
            int aC = (tid & 1) << 2;        // 0 or 4
            float4 va = *(const float4*)&A[(size_t)(bm + aR) * lda + k0 + aC];
            As[aC + 0][aR] = va.x; As[aC + 1][aR] = va.y;
            As[aC + 2][aR] = va.z; As[aC + 3][aR] = va.w;
        }
        if (BT) {
            int bN = tid >> 1;
            int bK = (tid & 1) << 2;
            float4 vb = *(const float4*)&B[(size_t)(bn + bN) * ldb + k0 + bK];
            Bs[bK + 0][bN] = vb.x; Bs[bK + 1][bN] = vb.y;
            Bs[bK + 2][bN] = vb.z; Bs[bK + 3][bN] = vb.w;
        } else {
            int bK = tid >> 5;
            int bN = (tid & 31) << 2;
            float4 vb = *(const float4*)&B[(size_t)(k0 + bK) * ldb + bn + bN];
            *(float4*)&Bs[bK][bN] = vb;
        }
        __syncthreads();
        #pragma unroll
        for (int kk = 0; kk < 8; kk++) {
            float a[8], b[8];
            *(float4*)&a[0] = *(const float4*)&As[kk][tr * 8 + 0];
            *(float4*)&a[4] = *(const float4*)&As[kk][tr * 8 + 4];
            *(float4*)&b[0] = *(const float4*)&Bs[kk][tc * 8 + 0];
            *(float4*)&b[4] = *(const float4*)&Bs[kk][tc * 8 + 4];
            #pragma unroll
            for (int i = 0; i < 8; i++)
                #pragma unroll
                for (int j = 0; j < 8; j++)
                    acc[i][j] += a[i] * b[j];
        }
        __syncthreads();
    }

    #pragma unroll
    for (int i = 0; i < 8; i++) {
        int m = bm + tr * 8 + i;
        float bv = BIAS ? bias[m] : 0.f;
        #pragma unroll
        for (int j = 0; j < 8; j += 4) {
            int n = bn + tc * 8 + j;
            float4 o;
            o.x = alpha * acc[i][j + 0] + bv;
            o.y = alpha * acc[i][j + 1] + bv;
            o.z = alpha * acc[i][j + 2] + bv;
            o.w = alpha * acc[i][j + 3] + bv;
            if (RES) {
                float4 r = *(const float4*)&resp[(size_t)m * N + n];
                o.x += r.x; o.y += r.y; o.z += r.z; o.w += r.w;
            }
            *(float4*)&C[(size_t)m * N + n] = o;
        }
    }
}

extern "C" void kernel_launch(void* const* d_in, const int* in_sizes, int n_in,
                              void* d_out, int out_size)
{
    const float* x     = (const float*)d_in[0];
    const float* gamma = (const float*)d_in[1];
    const float* beta  = (const float*)d_in[2];
    const float* wq    = (const float*)d_in[3];
    const float* bq    = (const float*)d_in[4];
    const float* wk    = (const float*)d_in[5];
    const float* bk    = (const float*)d_in[6];
    const float* wv    = (const float*)d_in[7];
    const float* bv    = (const float*)d_in[8];
    const float* wp    = (const float*)d_in[9];
    const float* bp    = (const float*)d_in[10];
    float* out = (float*)d_out;

    float *xn, *q, *k, *v, *e, *o;
    cudaGetSymbolAddress((void**)&xn, g_xn);
    cudaGetSymbolAddress((void**)&q,  g_q);
    cudaGetSymbolAddress((void**)&k,  g_k);
    cudaGetSymbolAddress((void**)&v,  g_v);
    cudaGetSymbolAddress((void**)&e,  g_e);
    cudaGetSymbolAddress((void**)&o,  g_o);

    const long long sX = (long long)CC * HWD;     // 512*1024
    const long long sE = (long long)HWD * HWD;    // 1024*1024
    const float scale = 0.044194173824159216f;    // 512^-0.5

    // 1) GroupNorm
    groupnorm_kernel<<<BB * NG, 256>>>(x, gamma, beta, xn);

    // 2) Q/K/V = W @ xn + b   (M=512, N=1024, K=512), batched over B
    dim3 gQ(HWD / 128, CC / 128, BB);
    gemm_kernel<false, false, true, false><<<gQ, 256>>>(wq, xn, q, bq, nullptr,
        CC, HWD, CC, CC, HWD, 0, sX, sX, 1.f);
    gemm_kernel<false, false, true, false><<<gQ, 256>>>(wk, xn, k, bk, nullptr,
        CC, HWD, CC, CC, HWD, 0, sX, sX, 1.f);
    gemm_kernel<false, false, true, false><<<gQ, 256>>>(wv, xn, v, bv, nullptr,
        CC, HWD, CC, CC, HWD, 0, sX, sX, 1.f);

    // 3) energy = scale * Q^T K   (M=1024, N=1024, K=512)
    dim3 gE(HWD / 128, HWD / 128, BB);
    gemm_kernel<true, false, false, false><<<gE, 256>>>(q, k, e, nullptr, nullptr,
        HWD, HWD, CC, HWD, HWD, sX, sX, sE, scale);

    // 4) softmax over last dim (rows of e)
    softmax_kernel<<<BB * HWD, 256>>>(e);

    // 5) o = V @ attn^T   (M=512, N=1024, K=1024); B(k,n)=attn[n*1024+k]
    dim3 gO(HWD / 128, CC / 128, BB);
    gemm_kernel<false, true, false, false><<<gO, 256>>>(v, e, o, nullptr, nullptr,
        CC, HWD, HWD, HWD, HWD, sX, sE, sX, 1.f);

    // 6) out = Wp @ o + bp + x
    gemm_kernel<false, false, true, true><<<gQ, 256>>>(wp, o, out, bp, x,
        CC, HWD, CC, CC, HWD, 0, sX, sX, 1.f);
}

// round 3
// speedup vs baseline: 1.7099x; 1.7099x over previous
#include <cuda_runtime.h>
#include <math.h>

#define BB 16
#define CC 512
#define HWD 1024
#define NG 32
#define CPG 16

// Scratch (allocation-free: __device__ globals)
__device__ float g_xn[(size_t)BB*CC*HWD];
__device__ float g_q [(size_t)BB*CC*HWD];
__device__ float g_k [(size_t)BB*CC*HWD];
__device__ float g_v [(size_t)BB*CC*HWD];
__device__ float g_e [(size_t)BB*HWD*HWD];
__device__ float g_o [(size_t)BB*CC*HWD];

// ---------------- GroupNorm ----------------
__global__ void groupnorm_kernel(const float* __restrict__ x,
                                 const float* __restrict__ gamma,
                                 const float* __restrict__ beta,
                                 float* __restrict__ out)
{
    int grp = blockIdx.x;
    int g = grp & 31;
    const int n = CPG * HWD;
    size_t base = (size_t)grp * CPG * HWD;
    const float* xp = x + base;
    float s = 0.f, ss = 0.f;
    for (int i = threadIdx.x; i < n; i += 256) {
        float v = xp[i];
        s += v; ss += v * v;
    }
    __shared__ float rs[256], rss[256];
    rs[threadIdx.x] = s; rss[threadIdx.x] = ss;
    __syncthreads();
    for (int off = 128; off > 0; off >>= 1) {
        if (threadIdx.x < off) {
            rs[threadIdx.x]  += rs[threadIdx.x + off];
            rss[threadIdx.x] += rss[threadIdx.x + off];
        }
        __syncthreads();
    }
    float mean = rs[0] / n;
    float var  = rss[0] / n - mean * mean;
    float inv  = rsqrtf(var + 1e-6f);
    float* op = out + base;
    for (int i = threadIdx.x; i < n; i += 256) {
        int c = g * CPG + (i >> 10);
        op[i] = (xp[i] - mean) * inv * gamma[c] + beta[c];
    }
}

// ---------------- Row softmax ----------------
__global__ void softmax_kernel(float* __restrict__ e)
{
    float4* r4 = (float4*)(e + (size_t)blockIdx.x * HWD);
    int t = threadIdx.x;
    float4 v = r4[t];
    float m = fmaxf(fmaxf(v.x, v.y), fmaxf(v.z, v.w));
    __shared__ float red[256];
    red[t] = m; __syncthreads();
    for (int off = 128; off > 0; off >>= 1) {
        if (t < off) red[t] = fmaxf(red[t], red[t + off]);
        __syncthreads();
    }
    m = red[0];
    __syncthreads();
    v.x = __expf(v.x - m); v.y = __expf(v.y - m);
    v.z = __expf(v.z - m); v.w = __expf(v.w - m);
    float s = v.x + v.y + v.z + v.w;
    red[t] = s; __syncthreads();
    for (int off = 128; off > 0; off >>= 1) {
        if (t < off) red[t] += red[t + off];
        __syncthreads();
    }
    float invs = 1.f / red[0];
    v.x *= invs; v.y *= invs; v.z *= invs; v.w *= invs;
    r4[t] = v;
}

// ---------------- TF32 tensor-core GEMM ----------------
// C[m,n] = alpha * sum_k A(m,k)*B(k,n) (+bias[m]) (+res[m,n])
// MODE 0 ("contig"):  element (r,k) at src[r*ld + k]
// MODE 1 ("strided"): element (r,k) at src[k*ld + r]
// Smem layout per 128x16 tile: S[r*16 + ((k%4)^swz(r))*4 + k/4] (tf32 bits)
// swz(r) = (r ^ (r>>2) ^ (r>>3)) & 3 -> LDS.128 fragment reads conflict-free,
// scatter STS <=4-way.

__device__ __forceinline__ unsigned f2tf(float f) {
    unsigned u; asm("cvt.rna.tf32.f32 %0, %1;" : "=r"(u) : "f"(f)); return u;
}

__device__ __forceinline__ void mma_tf32(float* c, unsigned a0, unsigned a1,
                                         unsigned a2, unsigned a3,
                                         unsigned b0, unsigned b1) {
    asm volatile(
        "mma.sync.aligned.m16n8k8.row.col.f32.tf32.tf32.f32 "
        "{%0,%1,%2,%3}, {%4,%5,%6,%7}, {%8,%9}, {%0,%1,%2,%3};"
        : "+f"(c[0]), "+f"(c[1]), "+f"(c[2]), "+f"(c[3])
        : "r"(a0), "r"(a1), "r"(a2), "r"(a3), "r"(b0), "r"(b1));
}

__device__ __forceinline__ int swz(int r) { return (r ^ (r >> 2) ^ (r >> 3)) & 3; }

template<int MODE>
__device__ __forceinline__ void ldg_tile(const float* __restrict__ src, int ld,
                                         int k0, int tid, float4 v[2])
{
    if (MODE == 0) {
        int r = tid >> 1;
        int jj0 = (tid & 1) * 2;
        const float* p = src + (size_t)r * ld + k0 + jj0 * 4;
        v[0] = *(const float4*)(p);
        v[1] = *(const float4*)(p + 4);
    } else {
        int k = tid >> 4;
        int mloc = tid & 15;
        const float* p = src + (size_t)(k0 + k) * ld + mloc * 8;
        v[0] = *(const float4*)(p);
        v[1] = *(const float4*)(p + 4);
    }
}

template<int MODE>
__device__ __forceinline__ void sts_tile(unsigned* __restrict__ S, int tid,
                                         const float4 v[2])
{
    const float* f = (const float*)v;
    if (MODE == 0) {
        int r = tid >> 1;
        int jj0 = (tid & 1) * 2;
        int s = swz(r);
        unsigned* row = S + r * 16;
        #pragma unroll
        for (int t = 0; t < 2; t++)
            #pragma unroll
            for (int i = 0; i < 4; i++)
                row[((i ^ s) << 2) + jj0 + t] = f2tf(f[t * 4 + i]);
    } else {
        int k = tid >> 4;
        int mloc = tid & 15;
        int kcol = (k & 3);
        int klo = (k >> 2);
        #pragma unroll
        for (int t = 0; t < 2; t++)
            #pragma unroll
            for (int e = 0; e < 4; e++) {
                int r = mloc * 8 + t * 4 + e;
                S[r * 16 + ((kcol ^ swz(r)) << 2) + klo] = f2tf(f[t * 4 + e]);
            }
    }
}

__device__ __forceinline__ void compute_tile(const unsigned* __restrict__ As,
                                             const unsigned* __restrict__ Bs,
                                             float acc[4][4][4],
                                             int m_base, int n_base, int lane)
{
    int g = lane >> 2, c = lane & 3;
    uint4 bf[4];
    #pragma unroll
    for (int ntl = 0; ntl < 4; ntl++) {
        int rn = n_base + ntl * 8 + g;
        bf[ntl] = *(const uint4*)&Bs[rn * 16 + ((c ^ swz(rn)) << 2)];
    }
    #pragma unroll
    for (int mtl = 0; mtl < 4; mtl++) {
        int r0 = m_base + mtl * 16 + g;
        int r1 = r0 + 8;
        uint4 a0 = *(const uint4*)&As[r0 * 16 + ((c ^ swz(r0)) << 2)];
        uint4 a1 = *(const uint4*)&As[r1 * 16 + ((c ^ swz(r1)) << 2)];
        #pragma unroll
        for (int ntl = 0; ntl < 4; ntl++) {
            mma_tf32(acc[mtl][ntl], a0.x, a1.x, a0.y, a1.y, bf[ntl].x, bf[ntl].y);
            mma_tf32(acc[mtl][ntl], a0.z, a1.z, a0.w, a1.w, bf[ntl].z, bf[ntl].w);
        }
    }
}

template<int AMODE, int BMODE, bool BIAS, bool RES>
__global__ void __launch_bounds__(256)
mma_gemm(const float* __restrict__ A, const float* __restrict__ B,
         float* __restrict__ C, const float* __restrict__ bias,
         const float* __restrict__ res,
         int N, int K, int lda, int ldb,
         long long sA, long long sB, long long sC, float alpha)
{
    __shared__ unsigned As[2][128 * 16];
    __shared__ unsigned Bs[2][128 * 16];

    long long z = blockIdx.z;
    const float* Ap = A + z * sA +
        (AMODE == 0 ? (size_t)blockIdx.y * 128 * lda : (size_t)blockIdx.y * 128);
    const float* Bp = B + z * sB +
        (BMODE == 0 ? (size_t)blockIdx.x * 128 * ldb : (size_t)blockIdx.x * 128);

    int tid = threadIdx.x;
    int lane = tid & 31, wid = tid >> 5;
    int m_base = (wid >> 2) * 64;
    int n_base = (wid & 3) * 32;

    float acc[4][4][4] = {};
    float4 va[2], vb[2];

    ldg_tile<AMODE>(Ap, lda, 0, tid, va);
    ldg_tile<BMODE>(Bp, ldb, 0, tid, vb);
    sts_tile<AMODE>(As[0], tid, va);
    sts_tile<BMODE>(Bs[0], tid, vb);
    __syncthreads();

    int NT = K >> 4;
    for (int kt = 0; kt < NT; kt++) {
        int cur = kt & 1;
        if (kt + 1 < NT) {
            ldg_tile<AMODE>(Ap, lda, (kt + 1) << 4, tid, va);
            ldg_tile<BMODE>(Bp, ldb, (kt + 1) << 4, tid, vb);
        }
        compute_tile(As[cur], Bs[cur], acc, m_base, n_base, lane);
        if (kt + 1 < NT) {
            sts_tile<AMODE>(As[cur ^ 1], tid, va);
            sts_tile<BMODE>(Bs[cur ^ 1], tid, vb);
            __syncthreads();
        }
    }

    // Epilogue
    int g = lane >> 2, c = lane & 3;
    float* Cp = C + z * sC;
    const float* resp = RES ? (res + z * sC) : nullptr;
    #pragma unroll
    for (int mtl = 0; mtl < 4; mtl++) {
        int m0 = blockIdx.y * 128 + m_base + mtl * 16 + g;
        int m1 = m0 + 8;
        float bv0 = BIAS ? bias[m0] : 0.f;
        float bv1 = BIAS ? bias[m1] : 0.f;
        #pragma unroll
        for (int ntl = 0; ntl < 4; ntl++) {
            int n = blockIdx.x * 128 + n_base + ntl * 8 + c * 2;
            float2 o0, o1;
            o0.x = alpha * acc[mtl][ntl][0] + bv0;
            o0.y = alpha * acc[mtl][ntl][1] + bv0;
            o1.x = alpha * acc[mtl][ntl][2] + bv1;
            o1.y = alpha * acc[mtl][ntl][3] + bv1;
            if (RES) {
                float2 r0 = *(const float2*)&resp[(size_t)m0 * N + n];
                float2 r1 = *(const float2*)&resp[(size_t)m1 * N + n];
                o0.x += r0.x; o0.y += r0.y;
                o1.x += r1.x; o1.y += r1.y;
            }
            *(float2*)&Cp[(size_t)m0 * N + n] = o0;
            *(float2*)&Cp[(size_t)m1 * N + n] = o1;
        }
    }
}

extern "C" void kernel_launch(void* const* d_in, const int* in_sizes, int n_in,
                              void* d_out, int out_size)
{
    const float* x     = (const float*)d_in[0];
    const float* gamma = (const float*)d_in[1];
    const float* beta  = (const float*)d_in[2];
    const float* wq    = (const float*)d_in[3];
    const float* bq    = (const float*)d_in[4];
    const float* wk    = (const float*)d_in[5];
    const float* bk    = (const float*)d_in[6];
    const float* wv    = (const float*)d_in[7];
    const float* bv    = (const float*)d_in[8];
    const float* wp    = (const float*)d_in[9];
    const float* bp    = (const float*)d_in[10];
    float* out = (float*)d_out;

    float *xn, *q, *k, *v, *e, *o;
    cudaGetSymbolAddress((void**)&xn, g_xn);
    cudaGetSymbolAddress((void**)&q,  g_q);
    cudaGetSymbolAddress((void**)&k,  g_k);
    cudaGetSymbolAddress((void**)&v,  g_v);
    cudaGetSymbolAddress((void**)&e,  g_e);
    cudaGetSymbolAddress((void**)&o,  g_o);

    const long long sX = (long long)CC * HWD;
    const long long sE = (long long)HWD * HWD;
    const float scale = 0.044194173824159216f;  // 512^-0.5

    // 1) GroupNorm
    groupnorm_kernel<<<BB * NG, 256>>>(x, gamma, beta, xn);

    // 2) Q/K/V = W @ xn + b : M=512, N=1024, K=512
    //    A=W contig (lda=512); B=xn strided (B(k,n)=xn[k*1024+n], ld=1024)
    dim3 gQ(HWD / 128, CC / 128, BB);
    mma_gemm<0, 1, true, false><<<gQ, 256>>>(wq, xn, q, bq, nullptr,
        HWD, CC, CC, HWD, 0, sX, sX, 1.f);
    mma_gemm<0, 1, true, false><<<gQ, 256>>>(wk, xn, k, bk, nullptr,
        HWD, CC, CC, HWD, 0, sX, sX, 1.f);
    mma_gemm<0, 1, true, false><<<gQ, 256>>>(wv, xn, v, bv, nullptr,
        HWD, CC, CC, HWD, 0, sX, sX, 1.f);

    // 3) energy = scale * Q^T K : M=1024, N=1024, K=512
    //    A=q strided (A(m,k)=q[k*1024+m]); B=k strided
    dim3 gE(HWD / 128, HWD / 128, BB);
    mma_gemm<1, 1, false, false><<<gE, 256>>>(q, k, e, nullptr, nullptr,
        HWD, CC, HWD, HWD, sX, sX, sE, scale);

    // 4) softmax over rows of e
    softmax_kernel<<<BB * HWD, 256>>>(e);

    // 5) o = V @ attn^T : M=512, N=1024, K=1024
    //    A=v contig (lda=1024); B=attn contig (B(k,n)=attn[n*1024+k], ld=1024)
    dim3 gO(HWD / 128, CC / 128, BB);
    mma_gemm<0, 0, false, false><<<gO, 256>>>(v, e, o, nullptr, nullptr,
        HWD, HWD, HWD, HWD, sX, sE, sX, 1.f);

    // 6) out = Wp @ o + bp + x
    mma_gemm<0, 1, true, true><<<gQ, 256>>>(wp, o, out, bp, x,
        HWD, CC, CC, HWD, 0, sX, sX, 1.f);
}

// round 6
// speedup vs baseline: 3.3585x; 1.9641x over previous
#include <cuda_runtime.h>
#include <cuda_bf16.h>
#include <math.h>
#include <stdint.h>

#define BB 16
#define CC 512
#define HWD 1024

// Scratch (allocation-free)
__device__ float g_xnt[(size_t)BB*HWD*CC];   // xn transposed: [b][hw][c]
__device__ float g_q  [(size_t)BB*HWD*CC];   // q token-major: [b][i][c]
__device__ float g_k  [(size_t)BB*HWD*CC];   // k token-major
__device__ float g_v  [(size_t)BB*CC*HWD];   // v channel-major: [b][c][j]
__device__ float g_e  [(size_t)BB*HWD*HWD];  // energy/attn [b][i][j]
__device__ float g_o  [(size_t)BB*HWD*CC];   // attn out token-major [b][i][c]

// ---------------- helpers ----------------
__device__ __forceinline__ uint32_t smem_u32(const void* p) {
    uint32_t a;
    asm("{ .reg .u64 t; cvta.to.shared.u64 t, %1; cvt.u32.u64 %0, t; }"
        : "=r"(a) : "l"(p));
    return a;
}
__device__ __forceinline__ uint32_t pk2(float a, float b) {
    __nv_bfloat162 t = __floats2bfloat162_rn(a, b);
    return *(uint32_t*)&t;
}
__device__ __forceinline__ void ldmx4(uint32_t* r, uint32_t addr) {
    asm volatile("ldmatrix.sync.aligned.m8n8.x4.shared.b16 {%0,%1,%2,%3}, [%4];"
                 : "=r"(r[0]), "=r"(r[1]), "=r"(r[2]), "=r"(r[3]) : "r"(addr));
}
__device__ __forceinline__ void mma_bf16(float* c, const uint32_t* a,
                                         uint32_t b0, uint32_t b1) {
    asm volatile(
        "mma.sync.aligned.m16n8k16.row.col.f32.bf16.bf16.f32 "
        "{%0,%1,%2,%3}, {%4,%5,%6,%7}, {%8,%9}, {%0,%1,%2,%3};"
        : "+f"(c[0]), "+f"(c[1]), "+f"(c[2]), "+f"(c[3])
        : "r"(a[0]), "r"(a[1]), "r"(a[2]), "r"(a[3]), "r"(b0), "r"(b1));
}
__device__ __forceinline__ void ld_pack(const float* g, uint4& u0, uint4& u1) {
    float4 v0 = *(const float4*)(g);
    float4 v1 = *(const float4*)(g + 4);
    float4 v2 = *(const float4*)(g + 8);
    float4 v3 = *(const float4*)(g + 12);
    u0.x = pk2(v0.x, v0.y); u0.y = pk2(v0.z, v0.w);
    u0.z = pk2(v1.x, v1.y); u0.w = pk2(v1.z, v1.w);
    u1.x = pk2(v2.x, v2.y); u1.y = pk2(v2.z, v2.w);
    u1.z = pk2(v3.x, v3.y); u1.w = pk2(v3.z, v3.w);
}

// ---------------- GroupNorm + transpose ----------------
// x: [b][c][hw] -> xn_t: [b][hw][c]
__global__ void groupnorm_t_kernel(const float* __restrict__ x,
                                   const float* __restrict__ gamma,
                                   const float* __restrict__ beta,
                                   float* __restrict__ out_t)
{
    int grp = blockIdx.x;            // b*32 + g
    int b = grp >> 5, g = grp & 31;
    const int n = 16 * HWD;
    const float* xp = x + (size_t)grp * n;
    int tid = threadIdx.x;

    float s = 0.f, ss = 0.f;
    for (int i = tid; i < n; i += 256) {
        float v = xp[i];
        s += v; ss += v * v;
    }
    __shared__ float rs[256], rss[256];
    rs[tid] = s; rss[tid] = ss;
    __syncthreads();
    for (int off = 128; off > 0; off >>= 1) {
        if (tid < off) { rs[tid] += rs[tid + off]; rss[tid] += rss[tid + off]; }
        __syncthreads();
    }
    float mean = rs[0] / n;
    float var  = rss[0] / n - mean * mean;
    float inv  = rsqrtf(var + 1e-6f);

    __shared__ float T[16][68];
    int c  = tid >> 4;
    int hl = (tid & 15) * 4;
    float gmul = gamma[g * 16 + c] * inv;
    float badd = beta[g * 16 + c] - mean * gmul;
    int hl2 = tid >> 2;
    int c2  = (tid & 3) * 4;
    float* orow_base = out_t + ((size_t)b * HWD) * CC + g * 16 + c2;
    __syncthreads();

    for (int hw0 = 0; hw0 < HWD; hw0 += 64) {
        float4 v = *(const float4*)&xp[c * HWD + hw0 + hl];
        T[c][hl + 0] = v.x * gmul + badd;
        T[c][hl + 1] = v.y * gmul + badd;
        T[c][hl + 2] = v.z * gmul + badd;
        T[c][hl + 3] = v.w * gmul + badd;
        __syncthreads();
        float4 o;
        o.x = T[c2 + 0][hl2];
        o.y = T[c2 + 1][hl2];
        o.z = T[c2 + 2][hl2];
        o.w = T[c2 + 3][hl2];
        *(float4*)&orow_base[(size_t)(hw0 + hl2) * CC] = o;
        __syncthreads();
    }
}

// ---------------- Row softmax ----------------
__global__ void softmax_kernel(float* __restrict__ e)
{
    float4* r4 = (float4*)(e + (size_t)blockIdx.x * HWD);
    int t = threadIdx.x;
    float4 v = r4[t];
    float m = fmaxf(fmaxf(v.x, v.y), fmaxf(v.z, v.w));
    __shared__ float red[256];
    red[t] = m; __syncthreads();
    for (int off = 128; off > 0; off >>= 1) {
        if (t < off) red[t] = fmaxf(red[t], red[t + off]);
        __syncthreads();
    }
    m = red[0];
    __syncthreads();
    v.x = __expf(v.x - m); v.y = __expf(v.y - m);
    v.z = __expf(v.z - m); v.w = __expf(v.w - m);
    float s = v.x + v.y + v.z + v.w;
    red[t] = s; __syncthreads();
    for (int off = 128; off > 0; off >>= 1) {
        if (t < off) red[t] += red[t + off];
        __syncthreads();
    }
    float invs = 1.f / red[0];
    v.x *= invs; v.y *= invs; v.z *= invs; v.w *= invs;
    r4[t] = v;
}

// ---------------- bf16 mma.sync GEMM ----------------
// C[m][n] = alpha * sum_k A[m*lda+k]*B[n*ldb+k] (+bias) (+res), C[m*ldc+n].
// Block tile 128x128, BK=32, bf16 operands in smem (80B padded rows),
// 8 warps, warp tile 64x32, m16n8k16, double buffered.
// BIASMODE: 0 none, 1 per-row(m), 2 per-col(n). RES: += res.

#define ROWB 80
#define TILEB (128 * ROWB)   // 10240

template<int BIASMODE, bool RES>
__global__ void __launch_bounds__(256, 2)
bf_gemm(const float* __restrict__ A, const float* __restrict__ B,
        float* __restrict__ C, const float* __restrict__ bias,
        const float* __restrict__ res,
        int K, int lda, int ldb, int ldc,
        long long sA, long long sB, long long sC, float alpha)
{
    __shared__ __align__(16) uint8_t smA[2][TILEB];
    __shared__ __align__(16) uint8_t smB[2][TILEB];
    __shared__ float bnCol[128];

    int tid = threadIdx.x, lane = tid & 31, wid = tid >> 5;
    long long z = blockIdx.z;
    int bm0 = blockIdx.y * 128;
    int bn0 = blockIdx.x * 128;
    const float* Ap = A + z * sA + (size_t)bm0 * lda;
    const float* Bp = B + z * sB + (size_t)bn0 * ldb;

    if (BIASMODE == 2 && tid < 128) bnCol[tid] = bias[bn0 + tid];

    int r = tid >> 1, h = tid & 1;          // row 0..127, k-half (16 floats)
    uint32_t stoff = (uint32_t)r * ROWB + h * 32;

    int m_base = (wid >> 2) * 64;           // 0 or 64
    int n_base = (wid & 3) * 32;            // 0..96
    uint32_t aBase = smem_u32(&smA[0][0]);
    uint32_t bBase = smem_u32(&smB[0][0]);
    uint32_t aoff = (uint32_t)(m_base + (lane & 7) + ((lane >> 3) & 1) * 8) * ROWB
                  + (lane >> 4) * 16;
    uint32_t boff = (uint32_t)(n_base + (lane & 7) + (lane >> 4) * 8) * ROWB
                  + ((lane >> 3) & 1) * 16;

    float acc[4][4][4] = {};
    uint4 ua0, ua1, ub0, ub1;

    // preload stage 0
    ld_pack(Ap + (size_t)r * lda + h * 16, ua0, ua1);
    ld_pack(Bp + (size_t)r * ldb + h * 16, ub0, ub1);
    *(uint4*)(&smA[0][stoff])      = ua0;
    *(uint4*)(&smA[0][stoff + 16]) = ua1;
    *(uint4*)(&smB[0][stoff])      = ub0;
    *(uint4*)(&smB[0][stoff + 16]) = ub1;
    __syncthreads();

    int NC = K >> 5;
    for (int i = 0; i < NC; i++) {
        int bs = i & 1;
        if (i + 1 < NC) {
            int k0 = (i + 1) << 5;
            ld_pack(Ap + (size_t)r * lda + k0 + h * 16, ua0, ua1);
            ld_pack(Bp + (size_t)r * ldb + k0 + h * 16, ub0, ub1);
        }
        uint32_t aS = aBase + bs * TILEB;
        uint32_t bS = bBase + bs * TILEB;
        #pragma unroll
        for (int ks = 0; ks < 2; ks++) {
            uint32_t af[4][4];
            #pragma unroll
            for (int mt = 0; mt < 4; mt++)
                ldmx4(af[mt], aS + aoff + mt * (16 * ROWB) + ks * 32);
            uint32_t bf[2][4];
            #pragma unroll
            for (int np = 0; np < 2; np++)
                ldmx4(bf[np], bS + boff + np * (16 * ROWB) + ks * 32);
            #pragma unroll
            for (int mt = 0; mt < 4; mt++)
                #pragma unroll
                for (int nt = 0; nt < 4; nt++)
                    mma_bf16(acc[mt][nt], af[mt],
                             bf[nt >> 1][(nt & 1) * 2],
                             bf[nt >> 1][(nt & 1) * 2 + 1]);
        }
        if (i + 1 < NC) {
            int ns = bs ^ 1;
            *(uint4*)(&smA[ns][stoff])      = ua0;
            *(uint4*)(&smA[ns][stoff + 16]) = ua1;
            *(uint4*)(&smB[ns][stoff])      = ub0;
            *(uint4*)(&smB[ns][stoff + 16]) = ub1;
            __syncthreads();
        }
    }

    // Epilogue: thread (g = lane>>2, c = lane&3)
    int g = lane >> 2, c = lane & 3;
    float* Cz = C + z * sC;
    const float* Rz = RES ? (res + z * sC) : (const float*)0;
    #pragma unroll
    for (int mt = 0; mt < 4; mt++) {
        int m0 = bm0 + m_base + mt * 16 + g;
        int m1 = m0 + 8;
        float bm_ = (BIASMODE == 1) ? bias[m0] : 0.f;
        float bm1 = (BIASMODE == 1) ? bias[m1] : 0.f;
        #pragma unroll
        for (int nt = 0; nt < 4; nt++) {
            int n = bn0 + n_base + nt * 8 + c * 2;
            float2 o0, o1;
            o0.x = alpha * acc[mt][nt][0];
            o0.y = alpha * acc[mt][nt][1];
            o1.x = alpha * acc[mt][nt][2];
            o1.y = alpha * acc[mt][nt][3];
            if (BIASMODE == 1) { o0.x += bm_; o0.y += bm_; o1.x += bm1; o1.y += bm1; }
            if (BIASMODE == 2) {
                float b0 = bnCol[n - bn0], b1 = bnCol[n - bn0 + 1];
                o0.x += b0; o0.y += b1; o1.x += b0; o1.y += b1;
            }
            if (RES) {
                float2 r0 = *(const float2*)&Rz[(size_t)m0 * ldc + n];
                float2 r1 = *(const float2*)&Rz[(size_t)m1 * ldc + n];
                o0.x += r0.x; o0.y += r0.y; o1.x += r1.x; o1.y += r1.y;
            }
            *(float2*)&Cz[(size_t)m0 * ldc + n] = o0;
            *(float2*)&Cz[(size_t)m1 * ldc + n] = o1;
        }
    }
}

extern "C" void kernel_launch(void* const* d_in, const int* in_sizes, int n_in,
                              void* d_out, int out_size)
{
    const float* x     = (const float*)d_in[0];
    const float* gamma = (const float*)d_in[1];
    const float* beta  = (const float*)d_in[2];
    const float* wq    = (const float*)d_in[3];
    const float* bq    = (const float*)d_in[4];
    const float* wk    = (const float*)d_in[5];
    const float* bk    = (const float*)d_in[6];
    const float* wv    = (const float*)d_in[7];
    const float* bv    = (const float*)d_in[8];
    const float* wp    = (const float*)d_in[9];
    const float* bp    = (const float*)d_in[10];
    float* out = (float*)d_out;

    float *xnt, *q, *k, *v, *e, *o;
    cudaGetSymbolAddress((void**)&xnt, g_xnt);
    cudaGetSymbolAddress((void**)&q,   g_q);
    cudaGetSymbolAddress((void**)&k,   g_k);
    cudaGetSymbolAddress((void**)&v,   g_v);
    cudaGetSymbolAddress((void**)&e,   g_e);
    cudaGetSymbolAddress((void**)&o,   g_o);

    const long long sX = (long long)CC * HWD;
    const long long sE = (long long)HWD * HWD;
    const float scale = 0.044194173824159216f;  // 512^-0.5

    // 1) GroupNorm + transpose -> xn_t[b][hw][c]
    groupnorm_t_kernel<<<BB * 32, 256>>>(x, gamma, beta, xnt);

    // 2) Q_t/K_t[i][c] = sum_k xn_t[i][k]*w[c][k] + b[c]  (M=1024, N=512, K=512)
    {
        dim3 g(CC / 128, HWD / 128, BB);
        bf_gemm<2, false><<<g, 256>>>(xnt, wq, q, bq, nullptr,
            CC, CC, CC, CC, sX, 0, sX, 1.f);
        bf_gemm<2, false><<<g, 256>>>(xnt, wk, k, bk, nullptr,
            CC, CC, CC, CC, sX, 0, sX, 1.f);
    }
    // 3) V_cm[c][j] = sum_k wv[c][k]*xn_t[j][k] + bv[c]   (M=512, N=1024, K=512)
    {
        dim3 g(HWD / 128, CC / 128, BB);
        bf_gemm<1, false><<<g, 256>>>(wv, xnt, v, bv, nullptr,
            CC, CC, CC, HWD, 0, sX, sX, 1.f);
    }
    // 4) E[i][j] = scale * sum_c Q_t[i][c]*K_t[j][c]      (M=1024, N=1024, K=512)
    {
        dim3 g(HWD / 128, HWD / 128, BB);
        bf_gemm<0, false><<<g, 256>>>(q, k, e, nullptr, nullptr,
            CC, CC, CC, HWD, sX, sX, sE, scale);
    }
    // 5) softmax rows of E
    softmax_kernel<<<BB * HWD, 256>>>(e);

    // 6) O_t[i][c] = sum_j attn[i][j]*V_cm[c][j]          (M=1024, N=512, K=1024)
    {
        dim3 g(CC / 128, HWD / 128, BB);
        bf_gemm<0, false><<<g, 256>>>(e, v, o, nullptr, nullptr,
            HWD, HWD, HWD, CC, sE, sX, sX, 1.f);
    }
    // 7) out[c][i] = sum_k wp[c][k]*O_t[i][k] + bp[c] + x[c][i]  (M=512, N=1024, K=512)
    {
        dim3 g(HWD / 128, CC / 128, BB);
        bf_gemm<1, true><<<g, 256>>>(wp, o, out, bp, x,
            CC, CC, CC, HWD, 0, sX, sX, 1.f);
    }
}

// round 7
// speedup vs baseline: 4.3659x; 1.3000x over previous
#include <cuda_runtime.h>
#include <cuda_bf16.h>
#include <math.h>
#include <stdint.h>

#define BB 16
#define CC 512
#define HWD 1024

typedef __nv_bfloat16 bf16;

// Scratch (allocation-free): bf16 operands, fp32 energy
__device__ bf16 gb_xnt[(size_t)BB*HWD*CC];   // groupnorm out, token-major [b][i][c]
__device__ bf16 gb_q  [(size_t)BB*HWD*CC];   // [b][i][c]
__device__ bf16 gb_k  [(size_t)BB*HWD*CC];   // [b][i][c]
__device__ bf16 gb_v  [(size_t)BB*CC*HWD];   // [b][c][j]
__device__ bf16 gb_a  [(size_t)BB*HWD*HWD];  // attn bf16 [b][i][j]
__device__ bf16 gb_o  [(size_t)BB*HWD*CC];   // [b][i][c]
__device__ float g_e  [(size_t)BB*HWD*HWD];  // energy fp32 [b][i][j]
__device__ bf16 gb_wq[(size_t)CC*CC];
__device__ bf16 gb_wk[(size_t)CC*CC];
__device__ bf16 gb_wv[(size_t)CC*CC];
__device__ bf16 gb_wp[(size_t)CC*CC];

// ---------------- helpers ----------------
__device__ __forceinline__ uint32_t smem_u32(const void* p) {
    uint32_t a;
    asm("{ .reg .u64 t; cvta.to.shared.u64 t, %1; cvt.u32.u64 %0, t; }"
        : "=r"(a) : "l"(p));
    return a;
}
__device__ __forceinline__ uint32_t pk2(float a, float b) {
    __nv_bfloat162 t = __floats2bfloat162_rn(a, b);
    return *(uint32_t*)&t;
}
__device__ __forceinline__ void ldmx4(uint32_t* r, uint32_t addr) {
    asm volatile("ldmatrix.sync.aligned.m8n8.x4.shared.b16 {%0,%1,%2,%3}, [%4];"
                 : "=r"(r[0]), "=r"(r[1]), "=r"(r[2]), "=r"(r[3]) : "r"(addr));
}
__device__ __forceinline__ void mma_bf16(float* c, const uint32_t* a,
                                         uint32_t b0, uint32_t b1) {
    asm volatile(
        "mma.sync.aligned.m16n8k16.row.col.f32.bf16.bf16.f32 "
        "{%0,%1,%2,%3}, {%4,%5,%6,%7}, {%8,%9}, {%0,%1,%2,%3};"
        : "+f"(c[0]), "+f"(c[1]), "+f"(c[2]), "+f"(c[3])
        : "r"(a[0]), "r"(a[1]), "r"(a[2]), "r"(a[3]), "r"(b0), "r"(b1));
}
__device__ __forceinline__ void cp16(uint32_t dst, const void* src) {
    asm volatile("cp.async.cg.shared.global [%0], [%1], 16;"
                 :: "r"(dst), "l"(src) : "memory");
}
__device__ __forceinline__ void cp_commit() {
    asm volatile("cp.async.commit_group;" ::: "memory");
}

// ---------------- weight convert (fp32 -> bf16) ----------------
__global__ void cvtw_kernel(const float* __restrict__ wq, const float* __restrict__ wk,
                            const float* __restrict__ wv, const float* __restrict__ wp,
                            bf16* oq, bf16* ok, bf16* ov, bf16* op)
{
    int i4 = (blockIdx.x * 256 + threadIdx.x) * 4;   // 65536 threads * 4 = 256K
    float4 a = *(const float4*)(wq + i4);
    float4 b = *(const float4*)(wk + i4);
    float4 c = *(const float4*)(wv + i4);
    float4 d = *(const float4*)(wp + i4);
    uint2 u;
    u.x = pk2(a.x, a.y); u.y = pk2(a.z, a.w); *(uint2*)(oq + i4) = u;
    u.x = pk2(b.x, b.y); u.y = pk2(b.z, b.w); *(uint2*)(ok + i4) = u;
    u.x = pk2(c.x, c.y); u.y = pk2(c.z, c.w); *(uint2*)(ov + i4) = u;
    u.x = pk2(d.x, d.y); u.y = pk2(d.z, d.w); *(uint2*)(op + i4) = u;
}

// ---------------- GroupNorm + transpose -> bf16 [b][hw][c] ----------------
__global__ void groupnorm_t_kernel(const float* __restrict__ x,
                                   const float* __restrict__ gamma,
                                   const float* __restrict__ beta,
                                   bf16* __restrict__ out_t)
{
    int grp = blockIdx.x;            // b*32 + g
    int b = grp >> 5, g = grp & 31;
    const int n = 16 * HWD;
    const float* xp = x + (size_t)grp * n;
    int tid = threadIdx.x;

    float s = 0.f, ss = 0.f;
    for (int i = tid; i < n; i += 256) {
        float v = xp[i];
        s += v; ss += v * v;
    }
    __shared__ float rs[256], rss[256];
    rs[tid] = s; rss[tid] = ss;
    __syncthreads();
    for (int off = 128; off > 0; off >>= 1) {
        if (tid < off) { rs[tid] += rs[tid + off]; rss[tid] += rss[tid + off]; }
        __syncthreads();
    }
    float mean = rs[0] / n;
    float var  = rss[0] / n - mean * mean;
    float inv  = rsqrtf(var + 1e-6f);

    __shared__ float T[16][68];
    int c  = tid >> 4;
    int hl = (tid & 15) * 4;
    float gmul = gamma[g * 16 + c] * inv;
    float badd = beta[g * 16 + c] - mean * gmul;
    int hl2 = tid >> 2;
    int c2  = (tid & 3) * 4;
    bf16* orow_base = out_t + ((size_t)b * HWD) * CC + g * 16 + c2;
    __syncthreads();

    for (int hw0 = 0; hw0 < HWD; hw0 += 64) {
        float4 v = *(const float4*)&xp[c * HWD + hw0 + hl];
        T[c][hl + 0] = v.x * gmul + badd;
        T[c][hl + 1] = v.y * gmul + badd;
        T[c][hl + 2] = v.z * gmul + badd;
        T[c][hl + 3] = v.w * gmul + badd;
        __syncthreads();
        uint2 pv;
        pv.x = pk2(T[c2 + 0][hl2], T[c2 + 1][hl2]);
        pv.y = pk2(T[c2 + 2][hl2], T[c2 + 3][hl2]);
        *(uint2*)&orow_base[(size_t)(hw0 + hl2) * CC] = pv;
        __syncthreads();
    }
}

// ---------------- Row softmax: e fp32 -> attn bf16 ----------------
__global__ void softmax_kernel(const float* __restrict__ e, bf16* __restrict__ a)
{
    const float4* r4 = (const float4*)(e + (size_t)blockIdx.x * HWD);
    int t = threadIdx.x;
    float4 v = r4[t];
    float m = fmaxf(fmaxf(v.x, v.y), fmaxf(v.z, v.w));
    __shared__ float red[256];
    red[t] = m; __syncthreads();
    for (int off = 128; off > 0; off >>= 1) {
        if (t < off) red[t] = fmaxf(red[t], red[t + off]);
        __syncthreads();
    }
    m = red[0];
    __syncthreads();
    v.x = __expf(v.x - m); v.y = __expf(v.y - m);
    v.z = __expf(v.z - m); v.w = __expf(v.w - m);
    float s = v.x + v.y + v.z + v.w;
    red[t] = s; __syncthreads();
    for (int off = 128; off > 0; off >>= 1) {
        if (t < off) red[t] += red[t + off];
        __syncthreads();
    }
    float invs = 1.f / red[0];
    uint2 o;
    o.x = pk2(v.x * invs, v.y * invs);
    o.y = pk2(v.z * invs, v.w * invs);
    *(uint2*)&a[(size_t)blockIdx.x * HWD + t * 4] = o;
}

// ---------------- bf16 mma.sync GEMM, cp.async 3-stage ----------------
// C[m][n] = alpha * sum_k A[m*lda+k]*B[n*ldb+k] (+bias) (+res)
// A, B bf16; block 128x128, BK=32, 4 warps (64x64 each), 80B-padded smem rows.
// BIASMODE: 0 none, 1 per-row(m), 2 per-col(n). RES: fp32 += res. OUTF32: C dtype.

#define ROWB 80
#define TILEB (128 * ROWB)     // 10240
#define STG   (2 * TILEB)      // A+B per stage = 20480
#define GSM   (3 * STG + 512)  // 61952

template<int BIASMODE, bool RES, bool OUTF32>
__global__ void __launch_bounds__(128, 2)
bf_gemm(const bf16* __restrict__ A, const bf16* __restrict__ B,
        void* __restrict__ Cv, const float* __restrict__ bias,
        const float* __restrict__ res,
        int K, int lda, int ldb, int ldc,
        long long sA, long long sB, long long sC, float alpha)
{
    extern __shared__ __align__(16) uint8_t sm[];
    uint32_t sb = smem_u32(sm);
    int tid = threadIdx.x, lane = tid & 31, wid = tid >> 5;
    int wm = (wid >> 1) * 64, wn = (wid & 1) * 64;
    long long z = blockIdx.z;
    int bm0 = blockIdx.y * 128, bn0 = blockIdx.x * 128;
    const bf16* Ap = A + z * sA + (size_t)bm0 * lda;
    const bf16* Bp = B + z * sB + (size_t)bn0 * ldb;

    float* bnCol = (float*)(sm + 3 * STG);
    if (BIASMODE == 2) bnCol[tid] = bias[bn0 + tid];

    // loader: thread t owns row t of both tiles (64B each)
    const char* gA = (const char*)(Ap + (size_t)tid * lda);
    const char* gB = (const char*)(Bp + (size_t)tid * ldb);
    uint32_t sAr = sb + tid * ROWB;
    uint32_t sBr = sb + TILEB + tid * ROWB;

    int NC = K >> 5;
    // prologue: stages 0,1
    #pragma unroll
    for (int s = 0; s < 2; s++) {
        #pragma unroll
        for (int u = 0; u < 4; u++) {
            cp16(sAr + s * STG + u * 16, gA + s * 64 + u * 16);
            cp16(sBr + s * STG + u * 16, gB + s * 64 + u * 16);
        }
        cp_commit();
    }

    uint32_t aoffL = (lane & 15) * ROWB + (lane >> 4) * 16;
    uint32_t boffL = ((lane & 7) + (lane >> 4) * 8) * ROWB + ((lane >> 3) & 1) * 16;

    float acc[4][8][4] = {};

    for (int i = 0; i < NC; i++) {
        if (i + 1 < NC) asm volatile("cp.async.wait_group 1;" ::: "memory");
        else            asm volatile("cp.async.wait_group 0;" ::: "memory");
        __syncthreads();
        if (i + 2 < NC) {
            int s = (i + 2) % 3;
            #pragma unroll
            for (int u = 0; u < 4; u++) {
                cp16(sAr + s * STG + u * 16, gA + (i + 2) * 64 + u * 16);
                cp16(sBr + s * STG + u * 16, gB + (i + 2) * 64 + u * 16);
            }
            cp_commit();
        }
        int s = i % 3;
        uint32_t aT = sb + s * STG + (uint32_t)wm * ROWB;
        uint32_t bT = sb + s * STG + TILEB + (uint32_t)wn * ROWB;
        #pragma unroll
        for (int ks = 0; ks < 2; ks++) {
            uint32_t af[4][4], bfr[4][4];
            #pragma unroll
            for (int mt = 0; mt < 4; mt++)
                ldmx4(af[mt], aT + mt * (16 * ROWB) + ks * 32 + aoffL);
            #pragma unroll
            for (int np = 0; np < 4; np++)
                ldmx4(bfr[np], bT + np * (16 * ROWB) + ks * 32 + boffL);
            #pragma unroll
            for (int mt = 0; mt < 4; mt++)
                #pragma unroll
                for (int nt = 0; nt < 8; nt++)
                    mma_bf16(acc[mt][nt], af[mt],
                             bfr[nt >> 1][(nt & 1) * 2],
                             bfr[nt >> 1][(nt & 1) * 2 + 1]);
        }
        __syncthreads();
    }

    // Epilogue
    int g = lane >> 2, c = lane & 3;
    #pragma unroll
    for (int mt = 0; mt < 4; mt++) {
        int m0 = bm0 + wm + mt * 16 + g;
        int m1 = m0 + 8;
        float bm_ = (BIASMODE == 1) ? bias[m0] : 0.f;
        float bm1 = (BIASMODE == 1) ? bias[m1] : 0.f;
        #pragma unroll
        for (int nt = 0; nt < 8; nt++) {
            int n = bn0 + wn + nt * 8 + c * 2;
            float o0x = alpha * acc[mt][nt][0];
            float o0y = alpha * acc[mt][nt][1];
            float o1x = alpha * acc[mt][nt][2];
            float o1y = alpha * acc[mt][nt][3];
            if (BIASMODE == 1) { o0x += bm_; o0y += bm_; o1x += bm1; o1y += bm1; }
            if (BIASMODE == 2) {
                float b0 = bnCol[n - bn0], b1 = bnCol[n - bn0 + 1];
                o0x += b0; o0y += b1; o1x += b0; o1y += b1;
            }
            if (OUTF32) {
                float* Cz = (float*)Cv + z * sC;
                if (RES) {
                    const float* Rz = res + z * sC;
                    float2 r0 = *(const float2*)&Rz[(size_t)m0 * ldc + n];
                    float2 r1 = *(const float2*)&Rz[(size_t)m1 * ldc + n];
                    o0x += r0.x; o0y += r0.y; o1x += r1.x; o1y += r1.y;
                }
                float2 w0 = {o0x, o0y}, w1 = {o1x, o1y};
                *(float2*)&Cz[(size_t)m0 * ldc + n] = w0;
                *(float2*)&Cz[(size_t)m1 * ldc + n] = w1;
            } else {
                bf16* Cz = (bf16*)Cv + z * sC;
                *(uint32_t*)&Cz[(size_t)m0 * ldc + n] = pk2(o0x, o0y);
                *(uint32_t*)&Cz[(size_t)m1 * ldc + n] = pk2(o1x, o1y);
            }
        }
    }
}

extern "C" void kernel_launch(void* const* d_in, const int* in_sizes, int n_in,
                              void* d_out, int out_size)
{
    const float* x     = (const float*)d_in[0];
    const float* gamma = (const float*)d_in[1];
    const float* beta  = (const float*)d_in[2];
    const float* wq    = (const float*)d_in[3];
    const float* bq    = (const float*)d_in[4];
    const float* wk    = (const float*)d_in[5];
    const float* bk    = (const float*)d_in[6];
    const float* wv    = (const float*)d_in[7];
    const float* bv    = (const float*)d_in[8];
    const float* wp    = (const float*)d_in[9];
    const float* bp    = (const float*)d_in[10];
    float* out = (float*)d_out;

    bf16 *xnt, *qb, *kb, *vb, *ab, *ob, *wqb, *wkb, *wvb, *wpb;
    float *e;
    cudaGetSymbolAddress((void**)&xnt, gb_xnt);
    cudaGetSymbolAddress((void**)&qb,  gb_q);
    cudaGetSymbolAddress((void**)&kb,  gb_k);
    cudaGetSymbolAddress((void**)&vb,  gb_v);
    cudaGetSymbolAddress((void**)&ab,  gb_a);
    cudaGetSymbolAddress((void**)&ob,  gb_o);
    cudaGetSymbolAddress((void**)&e,   g_e);
    cudaGetSymbolAddress((void**)&wqb, gb_wq);
    cudaGetSymbolAddress((void**)&wkb, gb_wk);
    cudaGetSymbolAddress((void**)&wvb, gb_wv);
    cudaGetSymbolAddress((void**)&wpb, gb_wp);

    cudaFuncSetAttribute(bf_gemm<2, false, false>, cudaFuncAttributeMaxDynamicSharedMemorySize, GSM);
    cudaFuncSetAttribute(bf_gemm<1, false, false>, cudaFuncAttributeMaxDynamicSharedMemorySize, GSM);
    cudaFuncSetAttribute(bf_gemm<0, false, true>,  cudaFuncAttributeMaxDynamicSharedMemorySize, GSM);
    cudaFuncSetAttribute(bf_gemm<0, false, false>, cudaFuncAttributeMaxDynamicSharedMemorySize, GSM);
    cudaFuncSetAttribute(bf_gemm<1, true, true>,   cudaFuncAttributeMaxDynamicSharedMemorySize, GSM);

    const long long sX = (long long)CC * HWD;   // 512K elts
    const long long sE = (long long)HWD * HWD;  // 1M elts
    const float scale = 0.044194173824159216f;  // 512^-0.5

    // 0) weights -> bf16
    cvtw_kernel<<<256, 256>>>(wq, wk, wv, wp, wqb, wkb, wvb, wpb);

    // 1) GroupNorm + transpose -> xnt bf16 [b][i][c]
    groupnorm_t_kernel<<<BB * 32, 256>>>(x, gamma, beta, xnt);

    // 2) Q/K[i][c] = sum_k xnt[i][k]*w[c][k] + b[c]   (M=1024, N=512, K=512)
    {
        dim3 g(CC / 128, HWD / 128, BB);
        bf_gemm<2, false, false><<<g, 128, GSM>>>(xnt, wqb, qb, bq, nullptr,
            CC, CC, CC, CC, sX, 0, sX, 1.f);
        bf_gemm<2, false, false><<<g, 128, GSM>>>(xnt, wkb, kb, bk, nullptr,
            CC, CC, CC, CC, sX, 0, sX, 1.f);
    }
    // 3) V[c][j] = sum_k wv[c][k]*xnt[j][k] + bv[c]   (M=512, N=1024, K=512)
    {
        dim3 g(HWD / 128, CC / 128, BB);
        bf_gemm<1, false, false><<<g, 128, GSM>>>(wvb, xnt, vb, bv, nullptr,
            CC, CC, CC, HWD, 0, sX, sX, 1.f);
    }
    // 4) E[i][j] = scale * sum_c Q[i][c]*K[j][c]      (M=1024, N=1024, K=512) fp32 out
    {
        dim3 g(HWD / 128, HWD / 128, BB);
        bf_gemm<0, false, true><<<g, 128, GSM>>>(qb, kb, e, nullptr, nullptr,
            CC, CC, CC, HWD, sX, sX, sE, scale);
    }
    // 5) softmax rows of E -> attn bf16
    softmax_kernel<<<BB * HWD, 256>>>(e, ab);

    // 6) O[i][c] = sum_j attn[i][j]*V[c][j]           (M=1024, N=512, K=1024)
    {
        dim3 g(CC / 128, HWD / 128, BB);
        bf_gemm<0, false, false><<<g, 128, GSM>>>(ab, vb, ob, nullptr, nullptr,
            HWD, HWD, HWD, CC, sE, sX, sX, 1.f);
    }
    // 7) out[c][i] = sum_k wp[c][k]*O[i][k] + bp[c] + x[c][i]  (M=512, N=1024, K=512)
    {
        dim3 g(HWD / 128, CC / 128, BB);
        bf_gemm<1, true, true><<<g, 128, GSM>>>(wpb, ob, out, bp, x,
            CC, CC, CC, HWD, 0, sX, sX, 1.f);
    }
}

// round 8
// speedup vs baseline: 4.6086x; 1.0556x over previous
#include <cuda_runtime.h>
#include <cuda_bf16.h>
#include <math.h>
#include <stdint.h>

#define BB 16
#define CC 512
#define HWD 1024

typedef __nv_bfloat16 bf16;

// Scratch (allocation-free): bf16 operands, fp32 energy
__device__ bf16 gb_xnt[(size_t)BB*HWD*CC];   // groupnorm out, token-major [b][i][c]
__device__ bf16 gb_q  [(size_t)BB*HWD*CC];   // [b][i][c]
__device__ bf16 gb_k  [(size_t)BB*HWD*CC];   // [b][i][c]
__device__ bf16 gb_v  [(size_t)BB*CC*HWD];   // [b][c][j]
__device__ bf16 gb_a  [(size_t)BB*HWD*HWD];  // attn bf16 [b][i][j]
__device__ bf16 gb_o  [(size_t)BB*HWD*CC];   // [b][i][c]
__device__ float g_e  [(size_t)BB*HWD*HWD];  // energy fp32 [b][i][j]
__device__ bf16 gb_wq[(size_t)CC*CC];
__device__ bf16 gb_wk[(size_t)CC*CC];
__device__ bf16 gb_wv[(size_t)CC*CC];
__device__ bf16 gb_wp[(size_t)CC*CC];

// ---------------- helpers ----------------
__device__ __forceinline__ uint32_t smem_u32(const void* p) {
    uint32_t a;
    asm("{ .reg .u64 t; cvta.to.shared.u64 t, %1; cvt.u32.u64 %0, t; }"
        : "=r"(a) : "l"(p));
    return a;
}
__device__ __forceinline__ uint32_t pk2(float a, float b) {
    __nv_bfloat162 t = __floats2bfloat162_rn(a, b);
    return *(uint32_t*)&t;
}
__device__ __forceinline__ void ldmx4(uint32_t* r, uint32_t addr) {
    asm volatile("ldmatrix.sync.aligned.m8n8.x4.shared.b16 {%0,%1,%2,%3}, [%4];"
                 : "=r"(r[0]), "=r"(r[1]), "=r"(r[2]), "=r"(r[3]) : "r"(addr));
}
__device__ __forceinline__ void mma_bf16(float* c, const uint32_t* a,
                                         uint32_t b0, uint32_t b1) {
    asm volatile(
        "mma.sync.aligned.m16n8k16.row.col.f32.bf16.bf16.f32 "
        "{%0,%1,%2,%3}, {%4,%5,%6,%7}, {%8,%9}, {%0,%1,%2,%3};"
        : "+f"(c[0]), "+f"(c[1]), "+f"(c[2]), "+f"(c[3])
        : "r"(a[0]), "r"(a[1]), "r"(a[2]), "r"(a[3]), "r"(b0), "r"(b1));
}
__device__ __forceinline__ void cp16(uint32_t dst, const void* src) {
    asm volatile("cp.async.cg.shared.global [%0], [%1], 16;"
                 :: "r"(dst), "l"(src) : "memory");
}
__device__ __forceinline__ void cp_commit() {
    asm volatile("cp.async.commit_group;" ::: "memory");
}

// ---------------- weight convert (fp32 -> bf16) ----------------
__global__ void cvtw_kernel(const float* __restrict__ wq, const float* __restrict__ wk,
                            const float* __restrict__ wv, const float* __restrict__ wp,
                            bf16* oq, bf16* ok, bf16* ov, bf16* op)
{
    int i4 = (blockIdx.x * 256 + threadIdx.x) * 4;
    float4 a = *(const float4*)(wq + i4);
    float4 b = *(const float4*)(wk + i4);
    float4 c = *(const float4*)(wv + i4);
    float4 d = *(const float4*)(wp + i4);
    uint2 u;
    u.x = pk2(a.x, a.y); u.y = pk2(a.z, a.w); *(uint2*)(oq + i4) = u;
    u.x = pk2(b.x, b.y); u.y = pk2(b.z, b.w); *(uint2*)(ok + i4) = u;
    u.x = pk2(c.x, c.y); u.y = pk2(c.z, c.w); *(uint2*)(ov + i4) = u;
    u.x = pk2(d.x, d.y); u.y = pk2(d.z, d.w); *(uint2*)(op + i4) = u;
}

// ---------------- GroupNorm + transpose -> bf16 [b][hw][c] ----------------
__global__ void groupnorm_t_kernel(const float* __restrict__ x,
                                   const float* __restrict__ gamma,
                                   const float* __restrict__ beta,
                                   bf16* __restrict__ out_t)
{
    int grp = blockIdx.x;            // b*32 + g
    int b = grp >> 5, g = grp & 31;
    const int n = 16 * HWD;
    const float* xp = x + (size_t)grp * n;
    int tid = threadIdx.x;

    float s = 0.f, ss = 0.f;
    for (int i = tid; i < n; i += 256) {
        float v = xp[i];
        s += v; ss += v * v;
    }
    __shared__ float rs[256], rss[256];
    rs[tid] = s; rss[tid] = ss;
    __syncthreads();
    for (int off = 128; off > 0; off >>= 1) {
        if (tid < off) { rs[tid] += rs[tid + off]; rss[tid] += rss[tid + off]; }
        __syncthreads();
    }
    float mean = rs[0] / n;
    float var  = rss[0] / n - mean * mean;
    float inv  = rsqrtf(var + 1e-6f);

    __shared__ float T[16][68];
    int c  = tid >> 4;
    int hl = (tid & 15) * 4;
    float gmul = gamma[g * 16 + c] * inv;
    float badd = beta[g * 16 + c] - mean * gmul;
    int hl2 = tid >> 2;
    int c2  = (tid & 3) * 4;
    bf16* orow_base = out_t + ((size_t)b * HWD) * CC + g * 16 + c2;
    __syncthreads();

    for (int hw0 = 0; hw0 < HWD; hw0 += 64) {
        float4 v = *(const float4*)&xp[c * HWD + hw0 + hl];
        T[c][hl + 0] = v.x * gmul + badd;
        T[c][hl + 1] = v.y * gmul + badd;
        T[c][hl + 2] = v.z * gmul + badd;
        T[c][hl + 3] = v.w * gmul + badd;
        __syncthreads();
        uint2 pv;
        pv.x = pk2(T[c2 + 0][hl2], T[c2 + 1][hl2]);
        pv.y = pk2(T[c2 + 2][hl2], T[c2 + 3][hl2]);
        *(uint2*)&orow_base[(size_t)(hw0 + hl2) * CC] = pv;
        __syncthreads();
    }
}

// ---------------- Row softmax: e fp32 -> attn bf16 ----------------
__global__ void softmax_kernel(const float* __restrict__ e, bf16* __restrict__ a)
{
    const float4* r4 = (const float4*)(e + (size_t)blockIdx.x * HWD);
    int t = threadIdx.x;
    float4 v = r4[t];
    float m = fmaxf(fmaxf(v.x, v.y), fmaxf(v.z, v.w));
    __shared__ float red[256];
    red[t] = m; __syncthreads();
    for (int off = 128; off > 0; off >>= 1) {
        if (t < off) red[t] = fmaxf(red[t], red[t + off]);
        __syncthreads();
    }
    m = red[0];
    __syncthreads();
    v.x = __expf(v.x - m); v.y = __expf(v.y - m);
    v.z = __expf(v.z - m); v.w = __expf(v.w - m);
    float s = v.x + v.y + v.z + v.w;
    red[t] = s; __syncthreads();
    for (int off = 128; off > 0; off >>= 1) {
        if (t < off) red[t] += red[t + off];
        __syncthreads();
    }
    float invs = 1.f / red[0];
    uint2 o;
    o.x = pk2(v.x * invs, v.y * invs);
    o.y = pk2(v.z * invs, v.w * invs);
    *(uint2*)&a[(size_t)blockIdx.x * HWD + t * 4] = o;
}

// ---------------- bf16 mma.sync GEMM, 4-stage cp.async, frag double-buffer ----
// C[m][n] = alpha * sum_k A[m*lda+k]*B[n*ldb+k] (+bias) (+res)
// A, B bf16; block 128x128, BK=32, 4 warps (64x64 each), 80B-padded smem rows.
// BIASMODE: 0 none, 1 per-row(m), 2 per-col(n). RES: fp32 += res. OUTF32: C dtype.

#define ROWB 80
#define TILEB (128 * ROWB)     // 10240
#define STG   (2 * TILEB)      // A+B per stage = 20480
#define GSM   (4 * STG + 512)  // 82432

template<int BIASMODE, bool RES, bool OUTF32>
__global__ void __launch_bounds__(128, 2)
bf_gemm(const bf16* __restrict__ A, const bf16* __restrict__ B,
        void* __restrict__ Cv, const float* __restrict__ bias,
        const float* __restrict__ res,
        int K, int lda, int ldb, int ldc,
        long long sA, long long sB, long long sC, float alpha)
{
    extern __shared__ __align__(16) uint8_t sm[];
    uint32_t sb = smem_u32(sm);
    int tid = threadIdx.x, lane = tid & 31, wid = tid >> 5;
    uint32_t wm = (wid >> 1) * 64, wn = (wid & 1) * 64;
    long long z = blockIdx.z;
    int bm0 = blockIdx.y * 128, bn0 = blockIdx.x * 128;
    const bf16* Ap = A + z * sA + (size_t)bm0 * lda;
    const bf16* Bp = B + z * sB + (size_t)bn0 * ldb;

    float* bnCol = (float*)(sm + 4 * STG);
    if (BIASMODE == 2) bnCol[tid] = bias[bn0 + tid];

    // loader: thread t owns row t of both tiles (64B per chunk)
    const char* gA = (const char*)(Ap + (size_t)tid * lda);
    const char* gB = (const char*)(Bp + (size_t)tid * ldb);
    uint32_t sAr = sb + tid * ROWB;
    uint32_t sBr = sb + TILEB + tid * ROWB;

    int NC = K >> 5;

    // prologue: fill stages 0..2
    #pragma unroll
    for (int s = 0; s < 3; s++) {
        #pragma unroll
        for (int u = 0; u < 4; u++) {
            cp16(sAr + s * STG + u * 16, gA + s * 64 + u * 16);
            cp16(sBr + s * STG + u * 16, gB + s * 64 + u * 16);
        }
        cp_commit();
    }
    asm volatile("cp.async.wait_group 2;" ::: "memory");
    __syncthreads();

    uint32_t aoffL = (lane & 15) * ROWB + (lane >> 4) * 16;
    uint32_t boffL = ((lane & 7) + (lane >> 4) * 8) * ROWB + ((lane >> 3) & 1) * 16;

    float acc[4][8][4] = {};
    uint32_t af0[4][4], bf0[4][4], af1[4][4], bf1[4][4];

    // preload ks=0 fragments of stage 0
    {
        uint32_t aT = sb + wm * ROWB + aoffL;
        uint32_t bT = sb + TILEB + wn * ROWB + boffL;
        #pragma unroll
        for (int mt = 0; mt < 4; mt++) ldmx4(af0[mt], aT + mt * (16 * ROWB));
        #pragma unroll
        for (int np = 0; np < 4; np++) ldmx4(bf0[np], bT + np * (16 * ROWB));
    }

    for (int i = 0; i < NC; i++) {
        uint32_t st = sb + (uint32_t)(i & 3) * STG;
        uint32_t aT = st + wm * ROWB + aoffL;
        uint32_t bT = st + TILEB + wn * ROWB + boffL;

        // load ks=1 fragments (latency hidden under ks=0 mma below)
        #pragma unroll
        for (int mt = 0; mt < 4; mt++) ldmx4(af1[mt], aT + mt * (16 * ROWB) + 32);
        #pragma unroll
        for (int np = 0; np < 4; np++) ldmx4(bf1[np], bT + np * (16 * ROWB) + 32);

        // mma ks=0
        #pragma unroll
        for (int mt = 0; mt < 4; mt++)
            #pragma unroll
            for (int nt = 0; nt < 8; nt++)
                mma_bf16(acc[mt][nt], af0[mt],
                         bf0[nt >> 1][(nt & 1) * 2], bf0[nt >> 1][(nt & 1) * 2 + 1]);

        // feed stage i+3
        if (i + 3 < NC) {
            uint32_t so = (uint32_t)((i + 3) & 3) * STG;
            #pragma unroll
            for (int u = 0; u < 4; u++) {
                cp16(sAr + so + u * 16, gA + (i + 3) * 64 + u * 16);
                cp16(sBr + so + u * 16, gB + (i + 3) * 64 + u * 16);
            }
            cp_commit();
        }

        // mma ks=1
        #pragma unroll
        for (int mt = 0; mt < 4; mt++)
            #pragma unroll
            for (int nt = 0; nt < 8; nt++)
                mma_bf16(acc[mt][nt], af1[mt],
                         bf1[nt >> 1][(nt & 1) * 2], bf1[nt >> 1][(nt & 1) * 2 + 1]);

        if (i + 1 < NC) {
            if (i + 3 < NC) asm volatile("cp.async.wait_group 2;" ::: "memory");
            else            asm volatile("cp.async.wait_group 0;" ::: "memory");
            __syncthreads();
            uint32_t s2 = sb + (uint32_t)((i + 1) & 3) * STG;
            uint32_t aT2 = s2 + wm * ROWB + aoffL;
            uint32_t bT2 = s2 + TILEB + wn * ROWB + boffL;
            #pragma unroll
            for (int mt = 0; mt < 4; mt++) ldmx4(af0[mt], aT2 + mt * (16 * ROWB));
            #pragma unroll
            for (int np = 0; np < 4; np++) ldmx4(bf0[np], bT2 + np * (16 * ROWB));
        }
    }

    // Epilogue
    int g = lane >> 2, c = lane & 3;
    #pragma unroll
    for (int mt = 0; mt < 4; mt++) {
        int m0 = bm0 + wm + mt * 16 + g;
        int m1 = m0 + 8;
        float bm_ = (BIASMODE == 1) ? bias[m0] : 0.f;
        float bm1 = (BIASMODE == 1) ? bias[m1] : 0.f;
        #pragma unroll
        for (int nt = 0; nt < 8; nt++) {
            int n = bn0 + wn + nt * 8 + c * 2;
            float o0x = alpha * acc[mt][nt][0];
            float o0y = alpha * acc[mt][nt][1];
            float o1x = alpha * acc[mt][nt][2];
            float o1y = alpha * acc[mt][nt][3];
            if (BIASMODE == 1) { o0x += bm_; o0y += bm_; o1x += bm1; o1y += bm1; }
            if (BIASMODE == 2) {
                float b0 = bnCol[n - bn0], b1 = bnCol[n - bn0 + 1];
                o0x += b0; o0y += b1; o1x += b0; o1y += b1;
            }
            if (OUTF32) {
                float* Cz = (float*)Cv + z * sC;
                if (RES) {
                    const float* Rz = res + z * sC;
                    float2 r0 = *(const float2*)&Rz[(size_t)m0 * ldc + n];
                    float2 r1 = *(const float2*)&Rz[(size_t)m1 * ldc + n];
                    o0x += r0.x; o0y += r0.y; o1x += r1.x; o1y += r1.y;
                }
                float2 w0 = {o0x, o0y}, w1 = {o1x, o1y};
                *(float2*)&Cz[(size_t)m0 * ldc + n] = w0;
                *(float2*)&Cz[(size_t)m1 * ldc + n] = w1;
            } else {
                bf16* Cz = (bf16*)Cv + z * sC;
                *(uint32_t*)&Cz[(size_t)m0 * ldc + n] = pk2(o0x, o0y);
                *(uint32_t*)&Cz[(size_t)m1 * ldc + n] = pk2(o1x, o1y);
            }
        }
    }
}

extern "C" void kernel_launch(void* const* d_in, const int* in_sizes, int n_in,
                              void* d_out, int out_size)
{
    const float* x     = (const float*)d_in[0];
    const float* gamma = (const float*)d_in[1];
    const float* beta  = (const float*)d_in[2];
    const float* wq    = (const float*)d_in[3];
    const float* bq    = (const float*)d_in[4];
    const float* wk    = (const float*)d_in[5];
    const float* bk    = (const float*)d_in[6];
    const float* wv    = (const float*)d_in[7];
    const float* bv    = (const float*)d_in[8];
    const float* wp    = (const float*)d_in[9];
    const float* bp    = (const float*)d_in[10];
    float* out = (float*)d_out;

    bf16 *xnt, *qb, *kb, *vb, *ab, *ob, *wqb, *wkb, *wvb, *wpb;
    float *e;
    cudaGetSymbolAddress((void**)&xnt, gb_xnt);
    cudaGetSymbolAddress((void**)&qb,  gb_q);
    cudaGetSymbolAddress((void**)&kb,  gb_k);
    cudaGetSymbolAddress((void**)&vb,  gb_v);
    cudaGetSymbolAddress((void**)&ab,  gb_a);
    cudaGetSymbolAddress((void**)&ob,  gb_o);
    cudaGetSymbolAddress((void**)&e,   g_e);
    cudaGetSymbolAddress((void**)&wqb, gb_wq);
    cudaGetSymbolAddress((void**)&wkb, gb_wk);
    cudaGetSymbolAddress((void**)&wvb, gb_wv);
    cudaGetSymbolAddress((void**)&wpb, gb_wp);

    cudaFuncSetAttribute(bf_gemm<2, false, false>, cudaFuncAttributeMaxDynamicSharedMemorySize, GSM);
    cudaFuncSetAttribute(bf_gemm<1, false, false>, cudaFuncAttributeMaxDynamicSharedMemorySize, GSM);
    cudaFuncSetAttribute(bf_gemm<0, false, true>,  cudaFuncAttributeMaxDynamicSharedMemorySize, GSM);
    cudaFuncSetAttribute(bf_gemm<0, false, false>, cudaFuncAttributeMaxDynamicSharedMemorySize, GSM);
    cudaFuncSetAttribute(bf_gemm<1, true, true>,   cudaFuncAttributeMaxDynamicSharedMemorySize, GSM);

    const long long sX = (long long)CC * HWD;   // 512K elts
    const long long sE = (long long)HWD * HWD;  // 1M elts
    const float scale = 0.044194173824159216f;  // 512^-0.5

    // 0) weights -> bf16
    cvtw_kernel<<<256, 256>>>(wq, wk, wv, wp, wqb, wkb, wvb, wpb);

    // 1) GroupNorm + transpose -> xnt bf16 [b][i][c]
    groupnorm_t_kernel<<<BB * 32, 256>>>(x, gamma, beta, xnt);

    // 2) Q/K[i][c] = sum_k xnt[i][k]*w[c][k] + b[c]   (M=1024, N=512, K=512)
    {
        dim3 g(CC / 128, HWD / 128, BB);
        bf_gemm<2, false, false><<<g, 128, GSM>>>(xnt, wqb, qb, bq, nullptr,
            CC, CC, CC, CC, sX, 0, sX, 1.f);
        bf_gemm<2, false, false><<<g, 128, GSM>>>(xnt, wkb, kb, bk, nullptr,
            CC, CC, CC, CC, sX, 0, sX, 1.f);
    }
    // 3) V[c][j] = sum_k wv[c][k]*xnt[j][k] + bv[c]   (M=512, N=1024, K=512)
    {
        dim3 g(HWD / 128, CC / 128, BB);
        bf_gemm<1, false, false><<<g, 128, GSM>>>(wvb, xnt, vb, bv, nullptr,
            CC, CC, CC, HWD, 0, sX, sX, 1.f);
    }
    // 4) E[i][j] = scale * sum_c Q[i][c]*K[j][c]      (M=1024, N=1024, K=512) fp32 out
    {
        dim3 g(HWD / 128, HWD / 128, BB);
        bf_gemm<0, false, true><<<g, 128, GSM>>>(qb, kb, e, nullptr, nullptr,
            CC, CC, CC, HWD, sX, sX, sE, scale);
    }
    // 5) softmax rows of E -> attn bf16
    softmax_kernel<<<BB * HWD, 256>>>(e, ab);

    // 6) O[i][c] = sum_j attn[i][j]*V[c][j]           (M=1024, N=512, K=1024)
    {
        dim3 g(CC / 128, HWD / 128, BB);
        bf_gemm<0, false, false><<<g, 128, GSM>>>(ab, vb, ob, nullptr, nullptr,
            HWD, HWD, HWD, CC, sE, sX, sX, 1.f);
    }
    // 7) out[c][i] = sum_k wp[c][k]*O[i][k] + bp[c] + x[c][i]  (M=512, N=1024, K=512)
    {
        dim3 g(HWD / 128, CC / 128, BB);
        bf_gemm<1, true, true><<<g, 128, GSM>>>(wpb, ob, out, bp, x,
            CC, CC, CC, HWD, 0, sX, sX, 1.f);
    }
}

// round 9
// speedup vs baseline: 5.1525x; 1.1180x over previous
#include <cuda_runtime.h>
#include <cuda_bf16.h>
#include <math.h>
#include <stdint.h>

#define BB 16
#define CC 512
#define HWD 1024

typedef __nv_bfloat16 bf16;

// Scratch (allocation-free): bf16 operands, fp32 energy
__device__ bf16 gb_xnt[(size_t)BB*HWD*CC];   // groupnorm out, token-major [b][i][c]
__device__ bf16 gb_q  [(size_t)BB*HWD*CC];   // [b][i][c]
__device__ bf16 gb_k  [(size_t)BB*HWD*CC];   // [b][i][c]
__device__ bf16 gb_v  [(size_t)BB*CC*HWD];   // [b][c][j]
__device__ bf16 gb_a  [(size_t)BB*HWD*HWD];  // attn bf16 [b][i][j]
__device__ bf16 gb_o  [(size_t)BB*HWD*CC];   // [b][i][c]
__device__ float g_e  [(size_t)BB*HWD*HWD];  // energy fp32 [b][i][j]
__device__ bf16 gb_wq[(size_t)CC*CC];
__device__ bf16 gb_wk[(size_t)CC*CC];
__device__ bf16 gb_wv[(size_t)CC*CC];
__device__ bf16 gb_wp[(size_t)CC*CC];

// ---------------- helpers ----------------
__device__ __forceinline__ uint32_t smem_u32(const void* p) {
    uint32_t a;
    asm("{ .reg .u64 t; cvta.to.shared.u64 t, %1; cvt.u32.u64 %0, t; }"
        : "=r"(a) : "l"(p));
    return a;
}
__device__ __forceinline__ uint32_t pk2(float a, float b) {
    __nv_bfloat162 t = __floats2bfloat162_rn(a, b);
    return *(uint32_t*)&t;
}
__device__ __forceinline__ void ldmx4(uint32_t* r, uint32_t addr) {
    asm volatile("ldmatrix.sync.aligned.m8n8.x4.shared.b16 {%0,%1,%2,%3}, [%4];"
                 : "=r"(r[0]), "=r"(r[1]), "=r"(r[2]), "=r"(r[3]) : "r"(addr));
}
__device__ __forceinline__ void mma_bf16(float* c, const uint32_t* a,
                                         uint32_t b0, uint32_t b1) {
    asm volatile(
        "mma.sync.aligned.m16n8k16.row.col.f32.bf16.bf16.f32 "
        "{%0,%1,%2,%3}, {%4,%5,%6,%7}, {%8,%9}, {%0,%1,%2,%3};"
        : "+f"(c[0]), "+f"(c[1]), "+f"(c[2]), "+f"(c[3])
        : "r"(a[0]), "r"(a[1]), "r"(a[2]), "r"(a[3]), "r"(b0), "r"(b1));
}
__device__ __forceinline__ void cp16(uint32_t dst, const void* src) {
    asm volatile("cp.async.cg.shared.global [%0], [%1], 16;"
                 :: "r"(dst), "l"(src) : "memory");
}
__device__ __forceinline__ void cp_commit() {
    asm volatile("cp.async.commit_group;" ::: "memory");
}

// ---------------- weight convert (fp32 -> bf16) ----------------
__global__ void cvtw_kernel(const float* __restrict__ wq, const float* __restrict__ wk,
                            const float* __restrict__ wv, const float* __restrict__ wp,
                            bf16* oq, bf16* ok, bf16* ov, bf16* op)
{
    int i4 = (blockIdx.x * 256 + threadIdx.x) * 4;
    float4 a = *(const float4*)(wq + i4);
    float4 b = *(const float4*)(wk + i4);
    float4 c = *(const float4*)(wv + i4);
    float4 d = *(const float4*)(wp + i4);
    uint2 u;
    u.x = pk2(a.x, a.y); u.y = pk2(a.z, a.w); *(uint2*)(oq + i4) = u;
    u.x = pk2(b.x, b.y); u.y = pk2(b.z, b.w); *(uint2*)(ok + i4) = u;
    u.x = pk2(c.x, c.y); u.y = pk2(c.z, c.w); *(uint2*)(ov + i4) = u;
    u.x = pk2(d.x, d.y); u.y = pk2(d.z, d.w); *(uint2*)(op + i4) = u;
}

// ---------------- GroupNorm + transpose -> bf16 [b][hw][c] ----------------
__global__ void groupnorm_t_kernel(const float* __restrict__ x,
                                   const float* __restrict__ gamma,
                                   const float* __restrict__ beta,
                                   bf16* __restrict__ out_t)
{
    int grp = blockIdx.x;            // b*32 + g
    int b = grp >> 5, g = grp & 31;
    const int n = 16 * HWD;
    const float* xp = x + (size_t)grp * n;
    int tid = threadIdx.x;

    float s = 0.f, ss = 0.f;
    for (int i = tid; i < n; i += 256) {
        float v = xp[i];
        s += v; ss += v * v;
    }
    __shared__ float rs[256], rss[256];
    rs[tid] = s; rss[tid] = ss;
    __syncthreads();
    for (int off = 128; off > 0; off >>= 1) {
        if (tid < off) { rs[tid] += rs[tid + off]; rss[tid] += rss[tid + off]; }
        __syncthreads();
    }
    float mean = rs[0] / n;
    float var  = rss[0] / n - mean * mean;
    float inv  = rsqrtf(var + 1e-6f);

    __shared__ float T[16][68];
    int c  = tid >> 4;
    int hl = (tid & 15) * 4;
    float gmul = gamma[g * 16 + c] * inv;
    float badd = beta[g * 16 + c] - mean * gmul;
    int hl2 = tid >> 2;
    int c2  = (tid & 3) * 4;
    bf16* orow_base = out_t + ((size_t)b * HWD) * CC + g * 16 + c2;
    __syncthreads();

    for (int hw0 = 0; hw0 < HWD; hw0 += 64) {
        float4 v = *(const float4*)&xp[c * HWD + hw0 + hl];
        T[c][hl + 0] = v.x * gmul + badd;
        T[c][hl + 1] = v.y * gmul + badd;
        T[c][hl + 2] = v.z * gmul + badd;
        T[c][hl + 3] = v.w * gmul + badd;
        __syncthreads();
        uint2 pv;
        pv.x = pk2(T[c2 + 0][hl2], T[c2 + 1][hl2]);
        pv.y = pk2(T[c2 + 2][hl2], T[c2 + 3][hl2]);
        *(uint2*)&orow_base[(size_t)(hw0 + hl2) * CC] = pv;
        __syncthreads();
    }
}

// ---------------- Row softmax: e fp32 -> attn bf16 ----------------
__global__ void softmax_kernel(const float* __restrict__ e, bf16* __restrict__ a)
{
    const float4* r4 = (const float4*)(e + (size_t)blockIdx.x * HWD);
    int t = threadIdx.x;
    float4 v = r4[t];
    float m = fmaxf(fmaxf(v.x, v.y), fmaxf(v.z, v.w));
    __shared__ float red[256];
    red[t] = m; __syncthreads();
    for (int off = 128; off > 0; off >>= 1) {
        if (t < off) red[t] = fmaxf(red[t], red[t + off]);
        __syncthreads();
    }
    m = red[0];
    __syncthreads();
    v.x = __expf(v.x - m); v.y = __expf(v.y - m);
    v.z = __expf(v.z - m); v.w = __expf(v.w - m);
    float s = v.x + v.y + v.z + v.w;
    red[t] = s; __syncthreads();
    for (int off = 128; off > 0; off >>= 1) {
        if (t < off) red[t] += red[t + off];
        __syncthreads();
    }
    float invs = 1.f / red[0];
    uint2 o;
    o.x = pk2(v.x * invs, v.y * invs);
    o.y = pk2(v.z * invs, v.w * invs);
    *(uint2*)&a[(size_t)blockIdx.x * HWD + t * 4] = o;
}

// ---------------- bf16 mma.sync GEMM: 256x128 tile, 4-stage cp.async --------
// C[m][n] = alpha * sum_k A[m*lda+k]*B[n*ldb+k] (+bias) (+res)
// A, B bf16; block 256(M)x128(N), BK=32, 8 warps (64x64 each), 80B-pad rows.
// BIASMODE: 0 none, 1 per-row(m), 2 per-col(n). RES: fp32 += res. OUTF32: C dtype.

#define ROWB 80
#define ATILEB (256 * ROWB)        // 20480
#define BTILEB (128 * ROWB)        // 10240
#define STG    (ATILEB + BTILEB)   // 30720
#define GSM    (4 * STG + 512)     // 123392

template<int BIASMODE, bool RES, bool OUTF32>
__global__ void __launch_bounds__(256, 1)
bf_gemm(const bf16* __restrict__ A, const bf16* __restrict__ B,
        void* __restrict__ Cv, const float* __restrict__ bias,
        const float* __restrict__ res,
        int K, int lda, int ldb, int ldc,
        long long sA, long long sB, long long sC, float alpha)
{
    extern __shared__ __align__(16) uint8_t sm[];
    uint32_t sb = smem_u32(sm);
    int tid = threadIdx.x, lane = tid & 31, wid = tid >> 5;
    uint32_t wm = (uint32_t)(wid >> 1) * 64;   // 0,64,128,192
    uint32_t wn = (uint32_t)(wid & 1) * 64;    // 0,64
    long long z = blockIdx.z;
    int bm0 = blockIdx.y * 256, bn0 = blockIdx.x * 128;
    const bf16* Ap = A + z * sA + (size_t)bm0 * lda;
    const bf16* Bp = B + z * sB + (size_t)bn0 * ldb;

    float* bnCol = (float*)(sm + 4 * STG);
    if (BIASMODE == 2 && tid < 128) bnCol[tid] = bias[bn0 + tid];

    // loader: A row = tid (64B/stage); B row = tid>>1, half (tid&1)*32B
    const char* gA = (const char*)(Ap + (size_t)tid * lda);
    const char* gB = (const char*)(Bp + (size_t)(tid >> 1) * ldb) + (tid & 1) * 32;
    uint32_t sAr = sb + (uint32_t)tid * ROWB;
    uint32_t sBr = sb + ATILEB + (uint32_t)(tid >> 1) * ROWB + (tid & 1) * 32;

    int NC = K >> 5;

    // prologue: fill stages 0..2
    #pragma unroll
    for (int s = 0; s < 3; s++) {
        #pragma unroll
        for (int u = 0; u < 4; u++)
            cp16(sAr + s * STG + u * 16, gA + s * 64 + u * 16);
        #pragma unroll
        for (int u = 0; u < 2; u++)
            cp16(sBr + s * STG + u * 16, gB + s * 64 + u * 16);
        cp_commit();
    }
    asm volatile("cp.async.wait_group 2;" ::: "memory");
    __syncthreads();

    uint32_t aoffL = (lane & 15) * ROWB + (lane >> 4) * 16;
    uint32_t boffL = ((lane & 7) + (lane >> 4) * 8) * ROWB + ((lane >> 3) & 1) * 16;

    float acc[4][8][4] = {};
    uint32_t af0[4][4], bf0[4][4], af1[4][4], bf1[4][4];

    // preload ks=0 fragments of stage 0
    {
        uint32_t aT = sb + wm * ROWB + aoffL;
        uint32_t bT = sb + ATILEB + wn * ROWB + boffL;
        #pragma unroll
        for (int mt = 0; mt < 4; mt++) ldmx4(af0[mt], aT + mt * (16 * ROWB));
        #pragma unroll
        for (int np = 0; np < 4; np++) ldmx4(bf0[np], bT + np * (16 * ROWB));
    }

    for (int i = 0; i < NC; i++) {
        uint32_t st = sb + (uint32_t)(i & 3) * STG;
        uint32_t aT = st + wm * ROWB + aoffL;
        uint32_t bT = st + ATILEB + wn * ROWB + boffL;

        // ks=1 fragment loads (hidden under ks=0 mma)
        #pragma unroll
        for (int mt = 0; mt < 4; mt++) ldmx4(af1[mt], aT + mt * (16 * ROWB) + 32);
        #pragma unroll
        for (int np = 0; np < 4; np++) ldmx4(bf1[np], bT + np * (16 * ROWB) + 32);

        // mma ks=0
        #pragma unroll
        for (int mt = 0; mt < 4; mt++)
            #pragma unroll
            for (int nt = 0; nt < 8; nt++)
                mma_bf16(acc[mt][nt], af0[mt],
                         bf0[nt >> 1][(nt & 1) * 2], bf0[nt >> 1][(nt & 1) * 2 + 1]);

        // feed stage i+3
        if (i + 3 < NC) {
            uint32_t so = (uint32_t)((i + 3) & 3) * STG;
            #pragma unroll
            for (int u = 0; u < 4; u++)
                cp16(sAr + so + u * 16, gA + (i + 3) * 64 + u * 16);
            #pragma unroll
            for (int u = 0; u < 2; u++)
                cp16(sBr + so + u * 16, gB + (i + 3) * 64 + u * 16);
            cp_commit();
        }

        // mma ks=1
        #pragma unroll
        for (int mt = 0; mt < 4; mt++)
            #pragma unroll
            for (int nt = 0; nt < 8; nt++)
                mma_bf16(acc[mt][nt], af1[mt],
                         bf1[nt >> 1][(nt & 1) * 2], bf1[nt >> 1][(nt & 1) * 2 + 1]);

        if (i + 1 < NC) {
            if (i + 3 < NC) asm volatile("cp.async.wait_group 2;" ::: "memory");
            else            asm volatile("cp.async.wait_group 0;" ::: "memory");
            __syncthreads();
            uint32_t s2 = sb + (uint32_t)((i + 1) & 3) * STG;
            uint32_t aT2 = s2 + wm * ROWB + aoffL;
            uint32_t bT2 = s2 + ATILEB + wn * ROWB + boffL;
            #pragma unroll
            for (int mt = 0; mt < 4; mt++) ldmx4(af0[mt], aT2 + mt * (16 * ROWB));
            #pragma unroll
            for (int np = 0; np < 4; np++) ldmx4(bf0[np], bT2 + np * (16 * ROWB));
        }
    }

    // Epilogue
    int g = lane >> 2, c = lane & 3;
    #pragma unroll
    for (int mt = 0; mt < 4; mt++) {
        int m0 = bm0 + (int)wm + mt * 16 + g;
        int m1 = m0 + 8;
        float bm_ = (BIASMODE == 1) ? bias[m0] : 0.f;
        float bm1 = (BIASMODE == 1) ? bias[m1] : 0.f;
        #pragma unroll
        for (int nt = 0; nt < 8; nt++) {
            int n = bn0 + (int)wn + nt * 8 + c * 2;
            float o0x = alpha * acc[mt][nt][0];
            float o0y = alpha * acc[mt][nt][1];
            float o1x = alpha * acc[mt][nt][2];
            float o1y = alpha * acc[mt][nt][3];
            if (BIASMODE == 1) { o0x += bm_; o0y += bm_; o1x += bm1; o1y += bm1; }
            if (BIASMODE == 2) {
                float b0 = bnCol[n - bn0], b1 = bnCol[n - bn0 + 1];
                o0x += b0; o0y += b1; o1x += b0; o1y += b1;
            }
            if (OUTF32) {
                float* Cz = (float*)Cv + z * sC;
                if (RES) {
                    const float* Rz = res + z * sC;
                    float2 r0 = *(const float2*)&Rz[(size_t)m0 * ldc + n];
                    float2 r1 = *(const float2*)&Rz[(size_t)m1 * ldc + n];
                    o0x += r0.x; o0y += r0.y; o1x += r1.x; o1y += r1.y;
                }
                float2 w0 = {o0x, o0y}, w1 = {o1x, o1y};
                *(float2*)&Cz[(size_t)m0 * ldc + n] = w0;
                *(float2*)&Cz[(size_t)m1 * ldc + n] = w1;
            } else {
                bf16* Cz = (bf16*)Cv + z * sC;
                *(uint32_t*)&Cz[(size_t)m0 * ldc + n] = pk2(o0x, o0y);
                *(uint32_t*)&Cz[(size_t)m1 * ldc + n] = pk2(o1x, o1y);
            }
        }
    }
}

extern "C" void kernel_launch(void* const* d_in, const int* in_sizes, int n_in,
                              void* d_out, int out_size)
{
    const float* x     = (const float*)d_in[0];
    const float* gamma = (const float*)d_in[1];
    const float* beta  = (const float*)d_in[2];
    const float* wq    = (const float*)d_in[3];
    const float* bq    = (const float*)d_in[4];
    const float* wk    = (const float*)d_in[5];
    const float* bk    = (const float*)d_in[6];
    const float* wv    = (const float*)d_in[7];
    const float* bv    = (const float*)d_in[8];
    const float* wp    = (const float*)d_in[9];
    const float* bp    = (const float*)d_in[10];
    float* out = (float*)d_out;

    bf16 *xnt, *qb, *kb, *vb, *ab, *ob, *wqb, *wkb, *wvb, *wpb;
    float *e;
    cudaGetSymbolAddress((void**)&xnt, gb_xnt);
    cudaGetSymbolAddress((void**)&qb,  gb_q);
    cudaGetSymbolAddress((void**)&kb,  gb_k);
    cudaGetSymbolAddress((void**)&vb,  gb_v);
    cudaGetSymbolAddress((void**)&ab,  gb_a);
    cudaGetSymbolAddress((void**)&ob,  gb_o);
    cudaGetSymbolAddress((void**)&e,   g_e);
    cudaGetSymbolAddress((void**)&wqb, gb_wq);
    cudaGetSymbolAddress((void**)&wkb, gb_wk);
    cudaGetSymbolAddress((void**)&wvb, gb_wv);
    cudaGetSymbolAddress((void**)&wpb, gb_wp);

    cudaFuncSetAttribute(bf_gemm<2, false, false>, cudaFuncAttributeMaxDynamicSharedMemorySize, GSM);
    cudaFuncSetAttribute(bf_gemm<1, false, false>, cudaFuncAttributeMaxDynamicSharedMemorySize, GSM);
    cudaFuncSetAttribute(bf_gemm<0, false, true>,  cudaFuncAttributeMaxDynamicSharedMemorySize, GSM);
    cudaFuncSetAttribute(bf_gemm<0, false, false>, cudaFuncAttributeMaxDynamicSharedMemorySize, GSM);
    cudaFuncSetAttribute(bf_gemm<1, true, true>,   cudaFuncAttributeMaxDynamicSharedMemorySize, GSM);

    const long long sX = (long long)CC * HWD;   // 512K elts
    const long long sE = (long long)HWD * HWD;  // 1M elts
    const float scale = 0.044194173824159216f;  // 512^-0.5

    // 0) weights -> bf16
    cvtw_kernel<<<256, 256>>>(wq, wk, wv, wp, wqb, wkb, wvb, wpb);

    // 1) GroupNorm + transpose -> xnt bf16 [b][i][c]
    groupnorm_t_kernel<<<BB * 32, 256>>>(x, gamma, beta, xnt);

    // 2) Q/K[i][c] = sum_k xnt[i][k]*w[c][k] + b[c]   (M=1024, N=512, K=512)
    {
        dim3 g(CC / 128, HWD / 256, BB);
        bf_gemm<2, false, false><<<g, 256, GSM>>>(xnt, wqb, qb, bq, nullptr,
            CC, CC, CC, CC, sX, 0, sX, 1.f);
        bf_gemm<2, false, false><<<g, 256, GSM>>>(xnt, wkb, kb, bk, nullptr,
            CC, CC, CC, CC, sX, 0, sX, 1.f);
    }
    // 3) V[c][j] = sum_k wv[c][k]*xnt[j][k] + bv[c]   (M=512, N=1024, K=512)
    {
        dim3 g(HWD / 128, CC / 256, BB);
        bf_gemm<1, false, false><<<g, 256, GSM>>>(wvb, xnt, vb, bv, nullptr,
            CC, CC, CC, HWD, 0, sX, sX, 1.f);
    }
    // 4) E[i][j] = scale * sum_c Q[i][c]*K[j][c]      (M=1024, N=1024, K=512) fp32 out
    {
        dim3 g(HWD / 128, HWD / 256, BB);
        bf_gemm<0, false, true><<<g, 256, GSM>>>(qb, kb, e, nullptr, nullptr,
            CC, CC, CC, HWD, sX, sX, sE, scale);
    }
    // 5) softmax rows of E -> attn bf16
    softmax_kernel<<<BB * HWD, 256>>>(e, ab);

    // 6) O[i][c] = sum_j attn[i][j]*V[c][j]           (M=1024, N=512, K=1024)
    {
        dim3 g(CC / 128, HWD / 256, BB);
        bf_gemm<0, false, false><<<g, 256, GSM>>>(ab, vb, ob, nullptr, nullptr,
            HWD, HWD, HWD, CC, sE, sX, sX, 1.f);
    }
    // 7) out[c][i] = sum_k wp[c][k]*O[i][k] + bp[c] + x[c][i]  (M=512, N=1024, K=512)
    {
        dim3 g(HWD / 128, CC / 256, BB);
        bf_gemm<1, true, true><<<g, 256, GSM>>>(wpb, ob, out, bp, x,
            CC, CC, CC, HWD, 0, sX, sX, 1.f);
    }
}

// round 10
// speedup vs baseline: 5.4717x; 1.0620x over previous
#include <cuda_runtime.h>
#include <cuda_bf16.h>
#include <math.h>
#include <stdint.h>

#define BB 16
#define CC 512
#define HWD 1024

typedef __nv_bfloat16 bf16;

// Scratch (allocation-free): bf16 operands, fp32 energy
__device__ bf16 gb_xnt[(size_t)BB*HWD*CC];   // groupnorm out, token-major [b][i][c]
__device__ bf16 gb_q  [(size_t)BB*HWD*CC];   // [b][i][c]
__device__ bf16 gb_k  [(size_t)BB*HWD*CC];   // [b][i][c]
__device__ bf16 gb_v  [(size_t)BB*CC*HWD];   // [b][c][j]
__device__ bf16 gb_a  [(size_t)BB*HWD*HWD];  // attn bf16 [b][i][j]
__device__ bf16 gb_o  [(size_t)BB*HWD*CC];   // [b][i][c]
__device__ float g_e  [(size_t)BB*HWD*HWD];  // energy fp32 [b][i][j]
__device__ bf16 gb_wq[(size_t)CC*CC];
__device__ bf16 gb_wk[(size_t)CC*CC];
__device__ bf16 gb_wv[(size_t)CC*CC];
__device__ bf16 gb_wp[(size_t)CC*CC];

// ---------------- helpers ----------------
__device__ __forceinline__ uint32_t smem_u32(const void* p) {
    uint32_t a;
    asm("{ .reg .u64 t; cvta.to.shared.u64 t, %1; cvt.u32.u64 %0, t; }"
        : "=r"(a) : "l"(p));
    return a;
}
__device__ __forceinline__ uint32_t pk2(float a, float b) {
    __nv_bfloat162 t = __floats2bfloat162_rn(a, b);
    return *(uint32_t*)&t;
}
__device__ __forceinline__ void ldmx4(uint32_t* r, uint32_t addr) {
    asm volatile("ldmatrix.sync.aligned.m8n8.x4.shared.b16 {%0,%1,%2,%3}, [%4];"
                 : "=r"(r[0]), "=r"(r[1]), "=r"(r[2]), "=r"(r[3]) : "r"(addr));
}
__device__ __forceinline__ void mma_bf16(float* c, const uint32_t* a,
                                         uint32_t b0, uint32_t b1) {
    asm volatile(
        "mma.sync.aligned.m16n8k16.row.col.f32.bf16.bf16.f32 "
        "{%0,%1,%2,%3}, {%4,%5,%6,%7}, {%8,%9}, {%0,%1,%2,%3};"
        : "+f"(c[0]), "+f"(c[1]), "+f"(c[2]), "+f"(c[3])
        : "r"(a[0]), "r"(a[1]), "r"(a[2]), "r"(a[3]), "r"(b0), "r"(b1));
}
__device__ __forceinline__ void cp16(uint32_t dst, const void* src) {
    asm volatile("cp.async.cg.shared.global [%0], [%1], 16;"
                 :: "r"(dst), "l"(src) : "memory");
}
__device__ __forceinline__ void cp_commit() {
    asm volatile("cp.async.commit_group;" ::: "memory");
}

// ---------------- weight convert (fp32 -> bf16) ----------------
__global__ void cvtw_kernel(const float* __restrict__ wq, const float* __restrict__ wk,
                            const float* __restrict__ wv, const float* __restrict__ wp,
                            bf16* oq, bf16* ok, bf16* ov, bf16* op)
{
    int i4 = (blockIdx.x * 256 + threadIdx.x) * 4;
    float4 a = *(const float4*)(wq + i4);
    float4 b = *(const float4*)(wk + i4);
    float4 c = *(const float4*)(wv + i4);
    float4 d = *(const float4*)(wp + i4);
    uint2 u;
    u.x = pk2(a.x, a.y); u.y = pk2(a.z, a.w); *(uint2*)(oq + i4) = u;
    u.x = pk2(b.x, b.y); u.y = pk2(b.z, b.w); *(uint2*)(ok + i4) = u;
    u.x = pk2(c.x, c.y); u.y = pk2(c.z, c.w); *(uint2*)(ov + i4) = u;
    u.x = pk2(d.x, d.y); u.y = pk2(d.z, d.w); *(uint2*)(op + i4) = u;
}

// ---------------- GroupNorm + transpose -> bf16 [b][hw][c] ----------------
__global__ void groupnorm_t_kernel(const float* __restrict__ x,
                                   const float* __restrict__ gamma,
                                   const float* __restrict__ beta,
                                   bf16* __restrict__ out_t)
{
    int grp = blockIdx.x;            // b*32 + g
    int b = grp >> 5, g = grp & 31;
    const int n = 16 * HWD;
    const float* xp = x + (size_t)grp * n;
    int tid = threadIdx.x;

    float s = 0.f, ss = 0.f;
    for (int i = tid; i < n; i += 256) {
        float v = xp[i];
        s += v; ss += v * v;
    }
    __shared__ float rs[256], rss[256];
    rs[tid] = s; rss[tid] = ss;
    __syncthreads();
    for (int off = 128; off > 0; off >>= 1) {
        if (tid < off) { rs[tid] += rs[tid + off]; rss[tid] += rss[tid + off]; }
        __syncthreads();
    }
    float mean = rs[0] / n;
    float var  = rss[0] / n - mean * mean;
    float inv  = rsqrtf(var + 1e-6f);

    __shared__ float T[16][68];
    int c  = tid >> 4;
    int hl = (tid & 15) * 4;
    float gmul = gamma[g * 16 + c] * inv;
    float badd = beta[g * 16 + c] - mean * gmul;
    int hl2 = tid >> 2;
    int c2  = (tid & 3) * 4;
    bf16* orow_base = out_t + ((size_t)b * HWD) * CC + g * 16 + c2;
    __syncthreads();

    for (int hw0 = 0; hw0 < HWD; hw0 += 64) {
        float4 v = *(const float4*)&xp[c * HWD + hw0 + hl];
        T[c][hl + 0] = v.x * gmul + badd;
        T[c][hl + 1] = v.y * gmul + badd;
        T[c][hl + 2] = v.z * gmul + badd;
        T[c][hl + 3] = v.w * gmul + badd;
        __syncthreads();
        uint2 pv;
        pv.x = pk2(T[c2 + 0][hl2], T[c2 + 1][hl2]);
        pv.y = pk2(T[c2 + 2][hl2], T[c2 + 3][hl2]);
        *(uint2*)&orow_base[(size_t)(hw0 + hl2) * CC] = pv;
        __syncthreads();
    }
}

// ---------------- Row softmax: e fp32 -> attn bf16 ----------------
__global__ void softmax_kernel(const float* __restrict__ e, bf16* __restrict__ a)
{
    const float4* r4 = (const float4*)(e + (size_t)blockIdx.x * HWD);
    int t = threadIdx.x;
    float4 v = r4[t];
    float m = fmaxf(fmaxf(v.x, v.y), fmaxf(v.z, v.w));
    __shared__ float red[256];
    red[t] = m; __syncthreads();
    for (int off = 128; off > 0; off >>= 1) {
        if (t < off) red[t] = fmaxf(red[t], red[t + off]);
        __syncthreads();
    }
    m = red[0];
    __syncthreads();
    v.x = __expf(v.x - m); v.y = __expf(v.y - m);
    v.z = __expf(v.z - m); v.w = __expf(v.w - m);
    float s = v.x + v.y + v.z + v.w;
    red[t] = s; __syncthreads();
    for (int off = 128; off > 0; off >>= 1) {
        if (t < off) red[t] += red[t + off];
        __syncthreads();
    }
    float invs = 1.f / red[0];
    uint2 o;
    o.x = pk2(v.x * invs, v.y * invs);
    o.y = pk2(v.z * invs, v.w * invs);
    *(uint2*)&a[(size_t)blockIdx.x * HWD + t * 4] = o;
}

// ---------------- bf16 mma.sync GEMM: 128x128 tile, 8 warps of 64x32 --------
// C[m][n] = alpha * sum_k A[m*lda+k]*B[n*ldb+k] (+bias) (+res)
// BK=32, 4-stage cp.async ring, 2 CTAs/SM (<=128 regs), 1 barrier/iter.
// BIASMODE: 0 none, 1 per-row(m), 2 per-col(n). RES: fp32 += res. OUTF32: C dtype.

#define ROWB 80
#define TILEB (128 * ROWB)     // 10240
#define STG   (2 * TILEB)      // 20480
#define GSM   (4 * STG + 512)  // 82432

template<int BIASMODE, bool RES, bool OUTF32>
__global__ void __launch_bounds__(256, 2)
bf_gemm(const bf16* __restrict__ A, const bf16* __restrict__ B,
        void* __restrict__ Cv, const float* __restrict__ bias,
        const float* __restrict__ res,
        int K, int lda, int ldb, int ldc,
        long long sA, long long sB, long long sC, float alpha)
{
    extern __shared__ __align__(16) uint8_t sm[];
    uint32_t sb = smem_u32(sm);
    int tid = threadIdx.x, lane = tid & 31, wid = tid >> 5;
    uint32_t wm = (uint32_t)(wid >> 2) * 64;   // 0,64
    uint32_t wn = (uint32_t)(wid & 3) * 32;    // 0,32,64,96
    long long z = blockIdx.z;
    int bm0 = blockIdx.y * 128, bn0 = blockIdx.x * 128;
    const bf16* Ap = A + z * sA + (size_t)bm0 * lda;
    const bf16* Bp = B + z * sB + (size_t)bn0 * ldb;

    float* bnCol = (float*)(sm + 4 * STG);
    if (BIASMODE == 2 && tid < 128) bnCol[tid] = bias[bn0 + tid];

    // loader: row = tid>>1 of both tiles, 32B half each
    const char* gA = (const char*)(Ap + (size_t)(tid >> 1) * lda) + (tid & 1) * 32;
    const char* gB = (const char*)(Bp + (size_t)(tid >> 1) * ldb) + (tid & 1) * 32;
    uint32_t sAr = sb + (uint32_t)(tid >> 1) * ROWB + (tid & 1) * 32;
    uint32_t sBr = sb + TILEB + (uint32_t)(tid >> 1) * ROWB + (tid & 1) * 32;

    int NC = K >> 5;

    // prologue: fill stages 0..2
    #pragma unroll
    for (int s = 0; s < 3; s++) {
        cp16(sAr + s * STG,      gA + s * 64);
        cp16(sAr + s * STG + 16, gA + s * 64 + 16);
        cp16(sBr + s * STG,      gB + s * 64);
        cp16(sBr + s * STG + 16, gB + s * 64 + 16);
        cp_commit();
    }

    uint32_t aoffL = (lane & 15) * ROWB + (lane >> 4) * 16;
    uint32_t boffL = ((lane & 7) + (lane >> 4) * 8) * ROWB + ((lane >> 3) & 1) * 16;

    float acc[4][4][4] = {};

    for (int i = 0; i < NC; i++) {
        if (i + 3 < NC) asm volatile("cp.async.wait_group 2;" ::: "memory");
        else            asm volatile("cp.async.wait_group 0;" ::: "memory");
        __syncthreads();

        uint32_t st = sb + (uint32_t)(i & 3) * STG;
        uint32_t aT = st + wm * ROWB + aoffL;
        uint32_t bT = st + TILEB + wn * ROWB + boffL;

        // ks = 0
        {
            uint32_t af[4][4], bfr[2][4];
            #pragma unroll
            for (int mt = 0; mt < 4; mt++) ldmx4(af[mt], aT + mt * (16 * ROWB));
            #pragma unroll
            for (int np = 0; np < 2; np++) ldmx4(bfr[np], bT + np * (16 * ROWB));
            #pragma unroll
            for (int mt = 0; mt < 4; mt++)
                #pragma unroll
                for (int nt = 0; nt < 4; nt++)
                    mma_bf16(acc[mt][nt], af[mt],
                             bfr[nt >> 1][(nt & 1) * 2], bfr[nt >> 1][(nt & 1) * 2 + 1]);
        }

        // feed stage i+3 (ring slot (i-1)&3; safe: bar above proved reads done)
        if (i + 3 < NC) {
            uint32_t so = (uint32_t)((i + 3) & 3) * STG;
            cp16(sAr + so,      gA + (i + 3) * 64);
            cp16(sAr + so + 16, gA + (i + 3) * 64 + 16);
            cp16(sBr + so,      gB + (i + 3) * 64);
            cp16(sBr + so + 16, gB + (i + 3) * 64 + 16);
            cp_commit();
        }

        // ks = 1
        {
            uint32_t af[4][4], bfr[2][4];
            #pragma unroll
            for (int mt = 0; mt < 4; mt++) ldmx4(af[mt], aT + mt * (16 * ROWB) + 32);
            #pragma unroll
            for (int np = 0; np < 2; np++) ldmx4(bfr[np], bT + np * (16 * ROWB) + 32);
            #pragma unroll
            for (int mt = 0; mt < 4; mt++)
                #pragma unroll
                for (int nt = 0; nt < 4; nt++)
                    mma_bf16(acc[mt][nt], af[mt],
                             bfr[nt >> 1][(nt & 1) * 2], bfr[nt >> 1][(nt & 1) * 2 + 1]);
        }
    }

    // Epilogue
    int g = lane >> 2, c = lane & 3;
    #pragma unroll
    for (int mt = 0; mt < 4; mt++) {
        int m0 = bm0 + (int)wm + mt * 16 + g;
        int m1 = m0 + 8;
        float bm_ = (BIASMODE == 1) ? bias[m0] : 0.f;
        float bm1 = (BIASMODE == 1) ? bias[m1] : 0.f;
        #pragma unroll
        for (int nt = 0; nt < 4; nt++) {
            int n = bn0 + (int)wn + nt * 8 + c * 2;
            float o0x = alpha * acc[mt][nt][0];
            float o0y = alpha * acc[mt][nt][1];
            float o1x = alpha * acc[mt][nt][2];
            float o1y = alpha * acc[mt][nt][3];
            if (BIASMODE == 1) { o0x += bm_; o0y += bm_; o1x += bm1; o1y += bm1; }
            if (BIASMODE == 2) {
                float b0 = bnCol[n - bn0], b1 = bnCol[n - bn0 + 1];
                o0x += b0; o0y += b1; o1x += b0; o1y += b1;
            }
            if (OUTF32) {
                float* Cz = (float*)Cv + z * sC;
                if (RES) {
                    const float* Rz = res + z * sC;
                    float2 r0 = *(const float2*)&Rz[(size_t)m0 * ldc + n];
                    float2 r1 = *(const float2*)&Rz[(size_t)m1 * ldc + n];
                    o0x += r0.x; o0y += r0.y; o1x += r1.x; o1y += r1.y;
                }
                float2 w0 = {o0x, o0y}, w1 = {o1x, o1y};
                *(float2*)&Cz[(size_t)m0 * ldc + n] = w0;
                *(float2*)&Cz[(size_t)m1 * ldc + n] = w1;
            } else {
                bf16* Cz = (bf16*)Cv + z * sC;
                *(uint32_t*)&Cz[(size_t)m0 * ldc + n] = pk2(o0x, o0y);
                *(uint32_t*)&Cz[(size_t)m1 * ldc + n] = pk2(o1x, o1y);
            }
        }
    }
}

extern "C" void kernel_launch(void* const* d_in, const int* in_sizes, int n_in,
                              void* d_out, int out_size)
{
    const float* x     = (const float*)d_in[0];
    const float* gamma = (const float*)d_in[1];
    const float* beta  = (const float*)d_in[2];
    const float* wq    = (const float*)d_in[3];
    const float* bq    = (const float*)d_in[4];
    const float* wk    = (const float*)d_in[5];
    const float* bk    = (const float*)d_in[6];
    const float* wv    = (const float*)d_in[7];
    const float* bv    = (const float*)d_in[8];
    const float* wp    = (const float*)d_in[9];
    const float* bp    = (const float*)d_in[10];
    float* out = (float*)d_out;

    bf16 *xnt, *qb, *kb, *vb, *ab, *ob, *wqb, *wkb, *wvb, *wpb;
    float *e;
    cudaGetSymbolAddress((void**)&xnt, gb_xnt);
    cudaGetSymbolAddress((void**)&qb,  gb_q);
    cudaGetSymbolAddress((void**)&kb,  gb_k);
    cudaGetSymbolAddress((void**)&vb,  gb_v);
    cudaGetSymbolAddress((void**)&ab,  gb_a);
    cudaGetSymbolAddress((void**)&ob,  gb_o);
    cudaGetSymbolAddress((void**)&e,   g_e);
    cudaGetSymbolAddress((void**)&wqb, gb_wq);
    cudaGetSymbolAddress((void**)&wkb, gb_wk);
    cudaGetSymbolAddress((void**)&wvb, gb_wv);
    cudaGetSymbolAddress((void**)&wpb, gb_wp);

    cudaFuncSetAttribute(bf_gemm<2, false, false>, cudaFuncAttributeMaxDynamicSharedMemorySize, GSM);
    cudaFuncSetAttribute(bf_gemm<1, false, false>, cudaFuncAttributeMaxDynamicSharedMemorySize, GSM);
    cudaFuncSetAttribute(bf_gemm<0, false, true>,  cudaFuncAttributeMaxDynamicSharedMemorySize, GSM);
    cudaFuncSetAttribute(bf_gemm<0, false, false>, cudaFuncAttributeMaxDynamicSharedMemorySize, GSM);
    cudaFuncSetAttribute(bf_gemm<1, true, true>,   cudaFuncAttributeMaxDynamicSharedMemorySize, GSM);

    const long long sX = (long long)CC * HWD;   // 512K elts
    const long long sE = (long long)HWD * HWD;  // 1M elts
    const float scale = 0.044194173824159216f;  // 512^-0.5

    // 0) weights -> bf16
    cvtw_kernel<<<256, 256>>>(wq, wk, wv, wp, wqb, wkb, wvb, wpb);

    // 1) GroupNorm + transpose -> xnt bf16 [b][i][c]
    groupnorm_t_kernel<<<BB * 32, 256>>>(x, gamma, beta, xnt);

    // 2) Q/K[i][c] = sum_k xnt[i][k]*w[c][k] + b[c]   (M=1024, N=512, K=512)
    {
        dim3 g(CC / 128, HWD / 128, BB);
        bf_gemm<2, false, false><<<g, 256, GSM>>>(xnt, wqb, qb, bq, nullptr,
            CC, CC, CC, CC, sX, 0, sX, 1.f);
        bf_gemm<2, false, false><<<g, 256, GSM>>>(xnt, wkb, kb, bk, nullptr,
            CC, CC, CC, CC, sX, 0, sX, 1.f);
    }
    // 3) V[c][j] = sum_k wv[c][k]*xnt[j][k] + bv[c]   (M=512, N=1024, K=512)
    {
        dim3 g(HWD / 128, CC / 128, BB);
        bf_gemm<1, false, false><<<g, 256, GSM>>>(wvb, xnt, vb, bv, nullptr,
            CC, CC, CC, HWD, 0, sX, sX, 1.f);
    }
    // 4) E[i][j] = scale * sum_c Q[i][c]*K[j][c]      (M=1024, N=1024, K=512) fp32 out
    {
        dim3 g(HWD / 128, HWD / 128, BB);
        bf_gemm<0, false, true><<<g, 256, GSM>>>(qb, kb, e, nullptr, nullptr,
            CC, CC, CC, HWD, sX, sX, sE, scale);
    }
    // 5) softmax rows of E -> attn bf16
    softmax_kernel<<<BB * HWD, 256>>>(e, ab);

    // 6) O[i][c] = sum_j attn[i][j]*V[c][j]           (M=1024, N=512, K=1024)
    {
        dim3 g(CC / 128, HWD / 128, BB);
        bf_gemm<0, false, false><<<g, 256, GSM>>>(ab, vb, ob, nullptr, nullptr,
            HWD, HWD, HWD, CC, sE, sX, sX, 1.f);
    }
    // 7) out[c][i] = sum_k wp[c][k]*O[i][k] + bp[c] + x[c][i]  (M=512, N=1024, K=512)
    {
        dim3 g(HWD / 128, CC / 128, BB);
        bf_gemm<1, true, true><<<g, 256, GSM>>>(wpb, ob, out, bp, x,
            CC, CC, CC, HWD, 0, sX, sX, 1.f);
    }
}